// round 11
// baseline (speedup 1.0000x reference)
#include <cuda_runtime.h>
#include <math.h>
#include <stdint.h>

#define SQn   2048
#define SKn   64
#define Cn    256
#define HWn   256
#define En    512
#define NPn   (SQn*SKn)
#define NHn   8
#define HDn   64

typedef unsigned long long u64;

__device__ __forceinline__ u64 fma2(u64 a, u64 b, u64 c) {
    u64 d;
    asm("fma.rn.f32x2 %0, %1, %2, %3;" : "=l"(d) : "l"(a), "l"(b), "l"(c));
    return d;
}
__device__ __forceinline__ u64 pack2(float lo, float hi) {
    u64 v;
    asm("mov.b64 %0, {%1, %2};" : "=l"(v) : "f"(lo), "f"(hi));
    return v;
}
__device__ __forceinline__ float2 unpack2(u64 v) {
    float lo, hi;
    asm("mov.b64 {%0, %1}, %2;" : "=f"(lo), "=f"(hi) : "l"(v));
    return make_float2(lo, hi);
}
__device__ __forceinline__ u64 splat2(float a) { return pack2(a, a); }

// ---------------- scratch ----------------
__device__ float g_Zt[(size_t)Cn*HWn*HWn];
__device__ float g_key2[(size_t)NPn*256];
__device__ float g_ql[(size_t)SQn*En];
__device__ float g_qk[(size_t)SQn*NHn*En];
__device__ float g_ctx[(size_t)SQn*NHn*En];
__device__ float g_out1[(size_t)SQn*En];

// ============ generic 64x64 f32x2 GEMM body (shared by qk / v / out) ============
// C[m][n] = sum_k A[m*lda+k] * B[n*ldbn + k*ldbk] + bias[n]
__device__ __forceinline__ void gemm64_body(
    float* As, float* Bs, int t,
    const float* __restrict__ A, int lda,
    const float* __restrict__ B, int ldbn, int ldbk,
    float* __restrict__ Cp, int ldc, const float* __restrict__ bias,
    int m0, int n0, int K)
{
    int tx = t & 15, ty = t >> 4;
    int ar = t >> 2, ac = (t & 3) * 4;
    const bool bvec = (ldbk == 1);
    const float* Abase = A + (long)(m0 + ar) * lda + ac;

    float4 ra = *(const float4*)Abase;
    float4 rb; float rbs[4];
    if (bvec) {
        rb = *(const float4*)(B + (long)(n0 + ar) * ldbn + ac);
    } else {
        #pragma unroll
        for (int q = 0; q < 4; q++) {
            int idx = t + 256*q; int nn = idx & 63, kk = idx >> 6;
            rbs[q] = B[(long)(n0 + nn) + (long)kk * ldbk];
        }
    }

    u64 acc2[2][4] = {};
    for (int k0 = 0; k0 < K; k0 += 16) {
        As[(ac+0)*68+ar]=ra.x; As[(ac+1)*68+ar]=ra.y; As[(ac+2)*68+ar]=ra.z; As[(ac+3)*68+ar]=ra.w;
        if (bvec) {
            Bs[(ac+0)*68+ar]=rb.x; Bs[(ac+1)*68+ar]=rb.y; Bs[(ac+2)*68+ar]=rb.z; Bs[(ac+3)*68+ar]=rb.w;
        } else {
            #pragma unroll
            for (int q = 0; q < 4; q++) {
                int idx = t + 256*q; int nn = idx & 63, kk = idx >> 6;
                Bs[kk*68+nn] = rbs[q];
            }
        }
        __syncthreads();
        if (k0 + 16 < K) {
            ra = *(const float4*)(Abase + k0 + 16);
            if (bvec) {
                rb = *(const float4*)(B + (long)(n0 + ar) * ldbn + k0 + 16 + ac);
            } else {
                #pragma unroll
                for (int q = 0; q < 4; q++) {
                    int idx = t + 256*q; int nn = idx & 63, kk = idx >> 6;
                    rbs[q] = B[(long)(n0 + nn) + (long)(k0 + 16 + kk) * ldbk];
                }
            }
        }
        #pragma unroll
        for (int k = 0; k < 16; k++) {
            ulonglong2 aP = *(const ulonglong2*)(&As[k*68 + ty*4]);
            float4 bq = *(const float4*)(&Bs[k*68 + tx*4]);
            u64 b0 = splat2(bq.x), b1 = splat2(bq.y), b2 = splat2(bq.z), b3 = splat2(bq.w);
            acc2[0][0]=fma2(aP.x,b0,acc2[0][0]); acc2[0][1]=fma2(aP.x,b1,acc2[0][1]);
            acc2[0][2]=fma2(aP.x,b2,acc2[0][2]); acc2[0][3]=fma2(aP.x,b3,acc2[0][3]);
            acc2[1][0]=fma2(aP.y,b0,acc2[1][0]); acc2[1][1]=fma2(aP.y,b1,acc2[1][1]);
            acc2[1][2]=fma2(aP.y,b2,acc2[1][2]); acc2[1][3]=fma2(aP.y,b3,acc2[1][3]);
        }
        __syncthreads();
    }
    float4 bb = make_float4(0.f,0.f,0.f,0.f);
    if (bias) bb = *(const float4*)(bias + n0 + tx*4);
    #pragma unroll
    for (int mp = 0; mp < 2; mp++) {
        float2 u0 = unpack2(acc2[mp][0]);
        float2 u1 = unpack2(acc2[mp][1]);
        float2 u2 = unpack2(acc2[mp][2]);
        float2 u3 = unpack2(acc2[mp][3]);
        int mA = m0 + ty*4 + mp*2, mB = mA + 1;
        *(float4*)(&Cp[(long)mA*ldc + n0 + tx*4]) =
            make_float4(u0.x+bb.x, u1.x+bb.y, u2.x+bb.z, u3.x+bb.w);
        *(float4*)(&Cp[(long)mB*ldc + n0 + tx*4]) =
            make_float4(u0.y+bb.x, u1.y+bb.y, u2.y+bb.z, u3.y+bb.w);
    }
}

__global__ __launch_bounds__(256)
void gemm64_kernel(const float* __restrict__ A, int lda, long sA,
                   const float* __restrict__ B, int ldbn, int ldbk, long sB,
                   float* __restrict__ Cp, int ldc, long sC,
                   const float* __restrict__ bias, long sBias, int K) {
    __shared__ float sm[2*16*68];
    int b = blockIdx.z;
    gemm64_body(sm, sm + 16*68, threadIdx.x,
                A + (long)b*sA, lda, B + (long)b*sB, ldbn, ldbk,
                Cp + (long)b*sC, ldc, bias ? bias + (long)b*sBias : (const float*)0,
                blockIdx.y*64, blockIdx.x*64, K);
}

// ============ K1: gemm1 (128x64 f32x2, fused query) + transpose ============
#define K1_GEMM 128
struct Gemm1S { float As[16][132]; float Bs[16][68]; };

__global__ __launch_bounds__(256)
void pre_kernel(const float* __restrict__ Z,
                const float* __restrict__ q_z,
                const float* __restrict__ Q,
                const float* __restrict__ w2,
                const float* __restrict__ b2,
                const float* __restrict__ in_proj_w,
                const float* __restrict__ in_proj_b) {
    __shared__ __align__(16) char smraw[sizeof(Gemm1S)];
    int bx = blockIdx.x, t = threadIdx.x;

    if (bx < K1_GEMM) {
        Gemm1S* S = (Gemm1S*)smraw;
        int tx = t & 15, ty = t >> 4;
        int m0 = (bx >> 3) * 128, n0 = (bx & 7) * 64;
        int ar = t >> 2, ac = (t & 3) * 4;
        int rowA = m0 + ar, rowB = rowA + 64;
        float qa0 = Q[rowA*3+0], qa1 = Q[rowA*3+1], qa2 = Q[rowA*3+2];
        float qb0 = Q[rowB*3+0], qb1 = Q[rowB*3+1], qb2 = Q[rowB*3+2];

        auto loadA = [&](int row, float q0, float q1, float q2, int k)->float4 {
            if (k < 256) return *(const float4*)(q_z + (long)row*256 + k);
            int h = k - 256;
            const float* w2r = w2 + h*3;
            float4 v;
            v.x = q0*w2r[0] + q1*w2r[1]  + q2*w2r[2]  + b2[h+0];
            v.y = q0*w2r[3] + q1*w2r[4]  + q2*w2r[5]  + b2[h+1];
            v.z = q0*w2r[6] + q1*w2r[7]  + q2*w2r[8]  + b2[h+2];
            v.w = q0*w2r[9] + q1*w2r[10] + q2*w2r[11] + b2[h+3];
            return v;
        };

        float4 ra0 = loadA(rowA, qa0, qa1, qa2, ac);
        float4 ra1 = loadA(rowB, qb0, qb1, qb2, ac);
        float4 rb  = *(const float4*)(in_proj_w + (long)(n0 + ar)*En + ac);

        u64 acc2[4][4] = {};
        for (int k0 = 0; k0 < En; k0 += 16) {
            S->As[ac+0][ar]=ra0.x; S->As[ac+1][ar]=ra0.y; S->As[ac+2][ar]=ra0.z; S->As[ac+3][ar]=ra0.w;
            S->As[ac+0][ar+64]=ra1.x; S->As[ac+1][ar+64]=ra1.y; S->As[ac+2][ar+64]=ra1.z; S->As[ac+3][ar+64]=ra1.w;
            S->Bs[ac+0][ar]=rb.x; S->Bs[ac+1][ar]=rb.y; S->Bs[ac+2][ar]=rb.z; S->Bs[ac+3][ar]=rb.w;
            __syncthreads();
            if (k0 + 16 < En) {
                ra0 = loadA(rowA, qa0, qa1, qa2, k0+16+ac);
                ra1 = loadA(rowB, qb0, qb1, qb2, k0+16+ac);
                rb  = *(const float4*)(in_proj_w + (long)(n0+ar)*En + k0+16+ac);
            }
            #pragma unroll
            for (int k = 0; k < 16; k++) {
                ulonglong2 aA = *(const ulonglong2*)(&S->As[k][ty*8]);
                ulonglong2 aB = *(const ulonglong2*)(&S->As[k][ty*8+4]);
                float4 bq = *(const float4*)(&S->Bs[k][tx*4]);
                u64 bs0=splat2(bq.x), bs1=splat2(bq.y), bs2=splat2(bq.z), bs3=splat2(bq.w);
                acc2[0][0]=fma2(aA.x,bs0,acc2[0][0]); acc2[0][1]=fma2(aA.x,bs1,acc2[0][1]);
                acc2[0][2]=fma2(aA.x,bs2,acc2[0][2]); acc2[0][3]=fma2(aA.x,bs3,acc2[0][3]);
                acc2[1][0]=fma2(aA.y,bs0,acc2[1][0]); acc2[1][1]=fma2(aA.y,bs1,acc2[1][1]);
                acc2[1][2]=fma2(aA.y,bs2,acc2[1][2]); acc2[1][3]=fma2(aA.y,bs3,acc2[1][3]);
                acc2[2][0]=fma2(aB.x,bs0,acc2[2][0]); acc2[2][1]=fma2(aB.x,bs1,acc2[2][1]);
                acc2[2][2]=fma2(aB.x,bs2,acc2[2][2]); acc2[2][3]=fma2(aB.x,bs3,acc2[2][3]);
                acc2[3][0]=fma2(aB.y,bs0,acc2[3][0]); acc2[3][1]=fma2(aB.y,bs1,acc2[3][1]);
                acc2[3][2]=fma2(aB.y,bs2,acc2[3][2]); acc2[3][3]=fma2(aB.y,bs3,acc2[3][3]);
            }
            __syncthreads();
        }
        float4 bb = *(const float4*)(in_proj_b + n0 + tx*4);
        #pragma unroll
        for (int mp = 0; mp < 4; mp++) {
            float2 u0=unpack2(acc2[mp][0]), u1=unpack2(acc2[mp][1]);
            float2 u2=unpack2(acc2[mp][2]), u3=unpack2(acc2[mp][3]);
            int mA = m0 + ty*8 + mp*2, mB = mA + 1;
            *(float4*)(&g_ql[(long)mA*En + n0 + tx*4]) =
                make_float4(u0.x+bb.x, u1.x+bb.y, u2.x+bb.z, u3.x+bb.w);
            *(float4*)(&g_ql[(long)mB*En + n0 + tx*4]) =
                make_float4(u0.y+bb.x, u1.y+bb.y, u2.y+bb.z, u3.y+bb.w);
        }
    } else {
        // transpose Z (C, HW*HW) -> Zt (HW*HW, C); 32x32 tiles
        float (*tile)[33] = (float(*)[33])smraw;
        int bi = bx - K1_GEMM;
        int xy0 = (bi & 2047) * 32;
        int c0  = (bi >> 11) * 32;
        int tx = t & 31, ty = t >> 5;   // 32 x 8
        #pragma unroll
        for (int i = 0; i < 32; i += 8)
            tile[ty + i][tx] = Z[(long)(c0 + ty + i)*(HWn*HWn) + xy0 + tx];
        __syncthreads();
        #pragma unroll
        for (int i = 0; i < 32; i += 8)
            g_Zt[(long)(xy0 + ty + i)*Cn + c0 + tx] = tile[tx][ty + i];
    }
}

// ============ K2: qk-gemm + qz->out copy + interp ============
#define K2_QK   2048
#define K2_CP   (K2_QK + 16)
struct InterpS { float sres[256][33]; int soff[32]; float sdx[32], sdy[32]; };

__global__ __launch_bounds__(256)
void mid_kernel(const float* __restrict__ r,
                const float* __restrict__ q_z,
                const float* __restrict__ in_proj_w,
                float* __restrict__ outp) {
    __shared__ __align__(16) char smraw[sizeof(InterpS)];
    int bx = blockIdx.x, t = threadIdx.x;

    if (bx < K2_QK) {
        // qk[b][h][n] = sum_d ql[b][h*64+d] * Wk[h*64+d][n]
        int ni = bx & 7, mi = (bx >> 3) & 31, h = bx >> 8;
        float* sm = (float*)smraw;
        gemm64_body(sm, sm + 16*68, t,
                    g_ql + (long)h*HDn, En,
                    in_proj_w + (long)En*En + (long)h*HDn*En, 1, En,
                    g_qk + (long)h*En, NHn*En, (const float*)0,
                    mi*64, ni*64, HDn);
    } else if (bx < K2_CP) {
        int r0 = (bx - K2_QK) * 128;
        #pragma unroll
        for (int i = 0; i < 32; i++) {
            int idx = i*256 + t;
            int row = r0 + (idx >> 6);
            int c4  = (idx & 63) * 4;
            *(float4*)(outp + (long)row*768 + c4) = *(const float4*)(q_z + (long)row*256 + c4);
        }
    } else {
        InterpS* S = (InterpS*)smraw;
        int p0 = (bx - K2_CP) * 32;
        if (t < 32) {
            float x = r[2*(p0+t)], y = r[2*(p0+t)+1];
            int x1 = (int)x, y1 = (int)y;
            S->soff[t] = (x1*HWn + y1)*Cn;
            S->sdx[t] = x - (float)x1;
            S->sdy[t] = y - (float)y1;
        }
        __syncthreads();
        int wp = t >> 5, l = t & 31;
        #pragma unroll
        for (int pi = 0; pi < 4; pi++) {
            int pl = wp*4 + pi;
            long off = S->soff[pl];
            float dx = S->sdx[pl], dy = S->sdy[pl];
            float omdx = 1.0f - dx, omdy = 1.0f - dy;
            #pragma unroll
            for (int rep = 0; rep < 2; rep++) {
                int c = rep*128 + l*4;
                const float* z11 = g_Zt + off + c;
                float4 a  = *(const float4*)(z11);
                float4 cq = *(const float4*)(z11 + Cn);
                float4 b  = *(const float4*)(z11 + HWn*Cn);
                float4 d  = *(const float4*)(z11 + HWn*Cn + Cn);
                S->sres[c+0][pl] = (a.x*omdx + b.x*dx)*omdy + (cq.x*omdx + d.x*dx)*dy;
                S->sres[c+1][pl] = (a.y*omdx + b.y*dx)*omdy + (cq.y*omdx + d.y*dx)*dy;
                S->sres[c+2][pl] = (a.z*omdx + b.z*dx)*omdy + (cq.z*omdx + d.z*dx)*dy;
                S->sres[c+3][pl] = (a.w*omdx + b.w*dx)*omdy + (cq.w*omdx + d.w*dx)*dy;
            }
        }
        __syncthreads();
        long rowhi = (long)(p0 >> 8);
        int  colb  = p0 & 255;
        #pragma unroll
        for (int i = 0; i < 32; i++) {
            int c = wp*32 + i;
            g_key2[((long)c*512 + rowhi)*256 + colb + l] = S->sres[c][l];
        }
    }
}

// ============ fused attention (unchanged from R8) ============
#define SKS 268
#define SQS 516
#define OFF_SQ   17152
#define OFF_RED  21280
#define OFF_SC   25376
#define OFF_SA   25888
#define OFF_SMAX 26400
#define OFF_SRS  26408
#define OFF_RXY  26416
#define OFF_W1E  26544
#define OFF_W1O  26800
#define OFF_B1S  27056
#define ATTN_FLTS 27312
#define ATTN_SMEM (ATTN_FLTS*4)

__global__ __launch_bounds__(256, 2)
void attn_kernel(const float* __restrict__ r, const float* __restrict__ w1,
                 const float* __restrict__ b1) {
    extern __shared__ float smf[];
    float* skey = smf;
    float* sq   = smf + OFF_SQ;
    float* red  = smf + OFF_RED;
    float* sc   = smf + OFF_SC;
    float* sa   = smf + OFF_SA;
    float* smax = smf + OFF_SMAX;
    float* srs  = smf + OFF_SRS;
    float* rxy  = smf + OFF_RXY;
    float* w1e  = smf + OFF_W1E;
    float* w1o  = smf + OFF_W1O;
    float* b1s  = smf + OFF_B1S;

    int b = blockIdx.x, t = threadIdx.x;

    const float* keyb = g_key2 + (long)b * (64*256);
    #pragma unroll
    for (int q = 0; q < 16; q++) {
        int idx = t + 256*q;
        int row = idx >> 6, c4 = (idx & 63) * 4;
        *(float4*)(skey + row*SKS + c4) = *(const float4*)(keyb + row*256 + c4);
    }
    {
        const float4* qsrc = (const float4*)(g_qk + (long)b * 4096);
        #pragma unroll
        for (int q = 0; q < 4; q++) {
            int idx = t + 256*q;
            int row = idx >> 7, c = idx & 127;
            *(float4*)(sq + row*SQS + c*4) = qsrc[row*128 + c];
        }
    }
    if (t < 128) rxy[t] = r[b*128 + t];
    w1e[t] = w1[2*t]; w1o[t] = w1[2*t+1]; b1s[t] = b1[t];
    __syncthreads();

    {
        int s = t >> 5, lane = t & 31;
        int hq = lane >> 4, kq = lane & 15;
        int h0 = hq * 4, jb = s * 32;
        u64 acc2[4][4] = {};
        #pragma unroll
        for (int st = 0; st < 8; st++) {
            int jj = jb + st*4;
            ulonglong2 a0 = *(const ulonglong2*)(sq + (h0+0)*SQS + jj);
            ulonglong2 a1 = *(const ulonglong2*)(sq + (h0+1)*SQS + jj);
            ulonglong2 a2 = *(const ulonglong2*)(sq + (h0+2)*SQS + jj);
            ulonglong2 a3 = *(const ulonglong2*)(sq + (h0+3)*SQS + jj);
            #pragma unroll
            for (int m = 0; m < 4; m++) {
                ulonglong2 bv = *(const ulonglong2*)(skey + (kq + 16*m)*SKS + jj);
                acc2[0][m] = fma2(a0.x, bv.x, acc2[0][m]); acc2[0][m] = fma2(a0.y, bv.y, acc2[0][m]);
                acc2[1][m] = fma2(a1.x, bv.x, acc2[1][m]); acc2[1][m] = fma2(a1.y, bv.y, acc2[1][m]);
                acc2[2][m] = fma2(a2.x, bv.x, acc2[2][m]); acc2[2][m] = fma2(a2.y, bv.y, acc2[2][m]);
                acc2[3][m] = fma2(a3.x, bv.x, acc2[3][m]); acc2[3][m] = fma2(a3.y, bv.y, acc2[3][m]);
            }
        }
        u64 xs[4], ys[4];
        #pragma unroll
        for (int m = 0; m < 4; m++) {
            int k = kq + 16*m;
            xs[m] = splat2(rxy[2*k]);
            ys[m] = splat2(rxy[2*k+1]);
        }
        #pragma unroll
        for (int st = 0; st < 8; st++) {
            int w = jb + st*4, jj = 256 + w;
            ulonglong2 a0 = *(const ulonglong2*)(sq + (h0+0)*SQS + jj);
            ulonglong2 a1 = *(const ulonglong2*)(sq + (h0+1)*SQS + jj);
            ulonglong2 a2 = *(const ulonglong2*)(sq + (h0+2)*SQS + jj);
            ulonglong2 a3 = *(const ulonglong2*)(sq + (h0+3)*SQS + jj);
            ulonglong2 we2 = *(const ulonglong2*)(w1e + w);
            ulonglong2 wo2 = *(const ulonglong2*)(w1o + w);
            ulonglong2 bc2 = *(const ulonglong2*)(b1s + w);
            #pragma unroll
            for (int m = 0; m < 4; m++) {
                u64 bv01 = fma2(xs[m], we2.x, fma2(ys[m], wo2.x, bc2.x));
                u64 bv23 = fma2(xs[m], we2.y, fma2(ys[m], wo2.y, bc2.y));
                acc2[0][m] = fma2(a0.x, bv01, acc2[0][m]); acc2[0][m] = fma2(a0.y, bv23, acc2[0][m]);
                acc2[1][m] = fma2(a1.x, bv01, acc2[1][m]); acc2[1][m] = fma2(a1.y, bv23, acc2[1][m]);
                acc2[2][m] = fma2(a2.x, bv01, acc2[2][m]); acc2[2][m] = fma2(a2.y, bv23, acc2[2][m]);
                acc2[3][m] = fma2(a3.x, bv01, acc2[3][m]); acc2[3][m] = fma2(a3.y, bv23, acc2[3][m]);
            }
        }
        #pragma unroll
        for (int hi = 0; hi < 4; hi++)
            #pragma unroll
            for (int m = 0; m < 4; m++) {
                float2 u = unpack2(acc2[hi][m]);
                red[s*512 + (h0+hi)*64 + m*16 + kq] = u.x + u.y;
            }
    }
    __syncthreads();
    #pragma unroll
    for (int e0 = 0; e0 < 2; e0++) {
        int e = t + e0*256;
        float v = 0.f;
        #pragma unroll
        for (int s2 = 0; s2 < 8; s2++) v += red[s2*512 + e];
        sc[e] = v * 0.125f;
    }
    __syncthreads();

    if (t < 32) {
        int h = t >> 2, seg = t & 3;
        const float* p = sc + h*64 + seg*16;
        float mx = p[0];
        #pragma unroll
        for (int i = 1; i < 16; i++) mx = fmaxf(mx, p[i]);
        mx = fmaxf(mx, __shfl_xor_sync(0xffffffffu, mx, 1));
        mx = fmaxf(mx, __shfl_xor_sync(0xffffffffu, mx, 2));
        float sm = 0.f;
        #pragma unroll
        for (int i = 0; i < 16; i++) sm += __expf(p[i] - mx);
        sm += __shfl_xor_sync(0xffffffffu, sm, 1);
        sm += __shfl_xor_sync(0xffffffffu, sm, 2);
        if (seg == 0) { smax[h] = mx; srs[h] = 1.0f / sm; }
    }
    __syncthreads();
    sa[t]     = __expf(sc[t]     - smax[t >> 6])       * srs[t >> 6];
    sa[t+256] = __expf(sc[t+256] - smax[(t+256) >> 6]) * srs[(t+256) >> 6];
    __syncthreads();

    {
        int hq = t >> 7, jq = t & 127;
        int h0 = hq * 4, j0 = jq * 4;
        const float* sa0 = sa + (h0+0)*64;
        const float* sa1 = sa + (h0+1)*64;
        const float* sa2 = sa + (h0+2)*64;
        const float* sa3 = sa + (h0+3)*64;
        u64 acc2[4][2] = {};
        if (j0 < 256) {
            #pragma unroll
            for (int k4 = 0; k4 < 64; k4 += 4) {
                float4 av0 = *(const float4*)(sa0 + k4);
                float4 av1 = *(const float4*)(sa1 + k4);
                float4 av2 = *(const float4*)(sa2 + k4);
                float4 av3 = *(const float4*)(sa3 + k4);
                float a0r[4] = {av0.x, av0.y, av0.z, av0.w};
                float a1r[4] = {av1.x, av1.y, av1.z, av1.w};
                float a2r[4] = {av2.x, av2.y, av2.z, av2.w};
                float a3r[4] = {av3.x, av3.y, av3.z, av3.w};
                #pragma unroll
                for (int kk = 0; kk < 4; kk++) {
                    ulonglong2 bv = *(const ulonglong2*)(skey + (k4+kk)*SKS + j0);
                    u64 s0 = splat2(a0r[kk]), s1 = splat2(a1r[kk]);
                    u64 s2 = splat2(a2r[kk]), s3 = splat2(a3r[kk]);
                    acc2[0][0]=fma2(s0,bv.x,acc2[0][0]); acc2[0][1]=fma2(s0,bv.y,acc2[0][1]);
                    acc2[1][0]=fma2(s1,bv.x,acc2[1][0]); acc2[1][1]=fma2(s1,bv.y,acc2[1][1]);
                    acc2[2][0]=fma2(s2,bv.x,acc2[2][0]); acc2[2][1]=fma2(s2,bv.y,acc2[2][1]);
                    acc2[3][0]=fma2(s3,bv.x,acc2[3][0]); acc2[3][1]=fma2(s3,bv.y,acc2[3][1]);
                }
            }
        } else {
            int w = j0 - 256;
            ulonglong2 we2 = *(const ulonglong2*)(w1e + w);
            ulonglong2 wo2 = *(const ulonglong2*)(w1o + w);
            ulonglong2 bc2 = *(const ulonglong2*)(b1s + w);
            #pragma unroll
            for (int k4 = 0; k4 < 64; k4 += 4) {
                float4 av0 = *(const float4*)(sa0 + k4);
                float4 av1 = *(const float4*)(sa1 + k4);
                float4 av2 = *(const float4*)(sa2 + k4);
                float4 av3 = *(const float4*)(sa3 + k4);
                float a0r[4] = {av0.x, av0.y, av0.z, av0.w};
                float a1r[4] = {av1.x, av1.y, av1.z, av1.w};
                float a2r[4] = {av2.x, av2.y, av2.z, av2.w};
                float a3r[4] = {av3.x, av3.y, av3.z, av3.w};
                #pragma unroll
                for (int kk = 0; kk < 4; kk++) {
                    int k = k4 + kk;
                    u64 xs = splat2(rxy[2*k]), ys = splat2(rxy[2*k+1]);
                    u64 bv01 = fma2(xs, we2.x, fma2(ys, wo2.x, bc2.x));
                    u64 bv23 = fma2(xs, we2.y, fma2(ys, wo2.y, bc2.y));
                    u64 s0 = splat2(a0r[kk]), s1 = splat2(a1r[kk]);
                    u64 s2 = splat2(a2r[kk]), s3 = splat2(a3r[kk]);
                    acc2[0][0]=fma2(s0,bv01,acc2[0][0]); acc2[0][1]=fma2(s0,bv23,acc2[0][1]);
                    acc2[1][0]=fma2(s1,bv01,acc2[1][0]); acc2[1][1]=fma2(s1,bv23,acc2[1][1]);
                    acc2[2][0]=fma2(s2,bv01,acc2[2][0]); acc2[2][1]=fma2(s2,bv23,acc2[2][1]);
                    acc2[3][0]=fma2(s3,bv01,acc2[3][0]); acc2[3][1]=fma2(s3,bv23,acc2[3][1]);
                }
            }
        }
        float* ctxb = g_ctx + (long)b * 4096;
        #pragma unroll
        for (int hi = 0; hi < 4; hi++) {
            float2 u0 = unpack2(acc2[hi][0]);
            float2 u1 = unpack2(acc2[hi][1]);
            *(float4*)(ctxb + (h0+hi)*512 + j0) = make_float4(u0.x, u0.y, u1.x, u1.y);
        }
    }
}

// ---------------- host launcher ----------------
extern "C" void kernel_launch(void* const* d_in, const int* in_sizes, int n_in,
                              void* d_out, int out_size) {
    const float* Z          = (const float*)d_in[0];
    const float* Q          = (const float*)d_in[1];
    const float* q_z        = (const float*)d_in[2];
    const float* r          = (const float*)d_in[3];
    const float* w1         = (const float*)d_in[4];
    const float* b1         = (const float*)d_in[5];
    const float* w2         = (const float*)d_in[6];
    const float* b2         = (const float*)d_in[7];
    const float* in_proj_w  = (const float*)d_in[8];
    const float* in_proj_b  = (const float*)d_in[9];
    const float* out_proj_w = (const float*)d_in[10];
    const float* out_proj_b = (const float*)d_in[11];
    float* outp = (float*)d_out;

    float *pCtx, *pOut1;
    cudaGetSymbolAddress((void**)&pCtx,  g_ctx);
    cudaGetSymbolAddress((void**)&pOut1, g_out1);

    cudaFuncSetAttribute(attn_kernel,
                         cudaFuncAttributeMaxDynamicSharedMemorySize, ATTN_SMEM);

    // K1: gemm1 (fused query) overlapped with Z transpose
    pre_kernel<<<K1_GEMM + 16384, 256>>>(Z, q_z, Q, w2, b2, in_proj_w, in_proj_b);

    // K2: qk-gemm overlapped with qz->out copy and bilinear interp
    mid_kernel<<<K2_CP + NPn/32, 256>>>(r, q_z, in_proj_w, outp);

    // K3: fused attention
    attn_kernel<<<SQn, 256, ATTN_SMEM>>>(r, w1, b1);

    // K4: out1[b][h*64+d] = ctx[b][h][:] . Wv[h*64+d][:] + bv
    gemm64_kernel<<<dim3(1, SQn/64, NHn), 256>>>(
        pCtx, NHn*En, (long)En,
        in_proj_w + (long)2*En*En, En, 1, (long)HDn*En,
        pOut1, En, (long)HDn,
        in_proj_b + (long)2*En, (long)HDn, En);

    // K5: final out_proj into d_out cols [256,768)
    gemm64_kernel<<<dim3(En/64, SQn/64, 1), 256>>>(
        pOut1, En, 0L,
        out_proj_w, En, 1, 0L,
        outp + 256, 768, 0L,
        out_proj_b, 0L, En);
}

// round 12
// speedup vs baseline: 1.0083x; 1.0083x over previous
#include <cuda_runtime.h>
#include <math.h>
#include <stdint.h>

#define SQn   2048
#define SKn   64
#define Cn    256
#define HWn   256
#define En    512
#define NPn   (SQn*SKn)
#define NHn   8
#define HDn   64

typedef unsigned long long u64;

__device__ __forceinline__ u64 fma2(u64 a, u64 b, u64 c) {
    u64 d;
    asm("fma.rn.f32x2 %0, %1, %2, %3;" : "=l"(d) : "l"(a), "l"(b), "l"(c));
    return d;
}
__device__ __forceinline__ u64 pack2(float lo, float hi) {
    u64 v;
    asm("mov.b64 %0, {%1, %2};" : "=l"(v) : "f"(lo), "f"(hi));
    return v;
}
__device__ __forceinline__ float2 unpack2(u64 v) {
    float lo, hi;
    asm("mov.b64 {%0, %1}, %2;" : "=f"(lo), "=f"(hi) : "l"(v));
    return make_float2(lo, hi);
}
__device__ __forceinline__ u64 splat2(float a) { return pack2(a, a); }

// ---------------- scratch ----------------
__device__ float g_Zt[(size_t)Cn*HWn*HWn];
__device__ float g_key2[(size_t)NPn*256];
__device__ float g_ql[(size_t)SQn*En];
__device__ float g_qk[(size_t)SQn*NHn*En];
__device__ float g_ctx[(size_t)SQn*NHn*En];
__device__ float g_out1[(size_t)SQn*En];
__device__ int   g_flags[64];

// flag layout:
// [0]      transpose done-count      (target 16384)
// [1..16]  gemm1 m-tile counts       (target 8 each)
// [17..32] attn chunk counts         (target 128 each)
// [33..48] v-gemm chunk counts       (target 8 each)
#define F_T 0
#define F_Q 1
#define F_A 17
#define F_V 33

__device__ __forceinline__ void flag_release(int idx, int t) {
    __syncthreads();
    __threadfence();
    if (t == 0) atomicAdd(&g_flags[idx], 1);
}
__device__ __forceinline__ void flag_acquire(int idx, int target, int t) {
    if (t == 0) {
        while (atomicAdd(&g_flags[idx], 0) < target) { }
        __threadfence();
    }
    __syncthreads();
}

// ============ proven 128x64 f32x2 GEMM body (R8) ============
// C[m][n] = sum_k A[m*lda+k] * B[n*ldbn + k*ldbk] + bias[n]
// As stride 132, Bs stride 68 (3200 floats total)
__device__ __forceinline__ void gemm128_body(
    float* As, float* Bs, int t,
    const float* __restrict__ A, int lda,
    const float* __restrict__ B, int ldbn, int ldbk,
    float* __restrict__ Cp, int ldc, const float* __restrict__ bias,
    int m0, int n0, int K)
{
    int tx = t & 15, ty = t >> 4;
    int ar = t >> 2, ac = (t & 3) * 4;
    const bool bvec = (ldbk == 1);
    const float* Abase = A + (long)(m0 + ar) * lda + ac;

    float4 ra0 = *(const float4*)(Abase);
    float4 ra1 = *(const float4*)(Abase + (long)64 * lda);
    float4 rb; float rbs[4];
    if (bvec) {
        rb = *(const float4*)(B + (long)(n0 + ar) * ldbn + ac);
    } else {
        #pragma unroll
        for (int q = 0; q < 4; q++) {
            int idx = t + 256*q; int nn = idx & 63, kk = idx >> 6;
            rbs[q] = B[(long)(n0 + nn) + (long)kk * ldbk];
        }
    }

    u64 acc2[4][4] = {};
    for (int k0 = 0; k0 < K; k0 += 16) {
        As[(ac+0)*132+ar]=ra0.x; As[(ac+1)*132+ar]=ra0.y; As[(ac+2)*132+ar]=ra0.z; As[(ac+3)*132+ar]=ra0.w;
        As[(ac+0)*132+ar+64]=ra1.x; As[(ac+1)*132+ar+64]=ra1.y; As[(ac+2)*132+ar+64]=ra1.z; As[(ac+3)*132+ar+64]=ra1.w;
        if (bvec) {
            Bs[(ac+0)*68+ar]=rb.x; Bs[(ac+1)*68+ar]=rb.y; Bs[(ac+2)*68+ar]=rb.z; Bs[(ac+3)*68+ar]=rb.w;
        } else {
            #pragma unroll
            for (int q = 0; q < 4; q++) {
                int idx = t + 256*q; int nn = idx & 63, kk = idx >> 6;
                Bs[kk*68+nn] = rbs[q];
            }
        }
        __syncthreads();
        if (k0 + 16 < K) {
            const float* An = Abase + k0 + 16;
            ra0 = *(const float4*)(An);
            ra1 = *(const float4*)(An + (long)64 * lda);
            if (bvec) {
                rb = *(const float4*)(B + (long)(n0 + ar) * ldbn + k0 + 16 + ac);
            } else {
                #pragma unroll
                for (int q = 0; q < 4; q++) {
                    int idx = t + 256*q; int nn = idx & 63, kk = idx >> 6;
                    rbs[q] = B[(long)(n0 + nn) + (long)(k0 + 16 + kk) * ldbk];
                }
            }
        }
        #pragma unroll
        for (int k = 0; k < 16; k++) {
            ulonglong2 aA = *(const ulonglong2*)(&As[k*132 + ty*8]);
            ulonglong2 aB = *(const ulonglong2*)(&As[k*132 + ty*8 + 4]);
            float4 bq = *(const float4*)(&Bs[k*68 + tx*4]);
            u64 bs0=splat2(bq.x), bs1=splat2(bq.y), bs2=splat2(bq.z), bs3=splat2(bq.w);
            acc2[0][0]=fma2(aA.x,bs0,acc2[0][0]); acc2[0][1]=fma2(aA.x,bs1,acc2[0][1]);
            acc2[0][2]=fma2(aA.x,bs2,acc2[0][2]); acc2[0][3]=fma2(aA.x,bs3,acc2[0][3]);
            acc2[1][0]=fma2(aA.y,bs0,acc2[1][0]); acc2[1][1]=fma2(aA.y,bs1,acc2[1][1]);
            acc2[1][2]=fma2(aA.y,bs2,acc2[1][2]); acc2[1][3]=fma2(aA.y,bs3,acc2[1][3]);
            acc2[2][0]=fma2(aB.x,bs0,acc2[2][0]); acc2[2][1]=fma2(aB.x,bs1,acc2[2][1]);
            acc2[2][2]=fma2(aB.x,bs2,acc2[2][2]); acc2[2][3]=fma2(aB.x,bs3,acc2[2][3]);
            acc2[3][0]=fma2(aB.y,bs0,acc2[3][0]); acc2[3][1]=fma2(aB.y,bs1,acc2[3][1]);
            acc2[3][2]=fma2(aB.y,bs2,acc2[3][2]); acc2[3][3]=fma2(aB.y,bs3,acc2[3][3]);
        }
        __syncthreads();
    }
    float4 bb = make_float4(0.f,0.f,0.f,0.f);
    if (bias) bb = *(const float4*)(bias + n0 + tx*4);
    #pragma unroll
    for (int mp = 0; mp < 4; mp++) {
        float2 u0=unpack2(acc2[mp][0]), u1=unpack2(acc2[mp][1]);
        float2 u2=unpack2(acc2[mp][2]), u3=unpack2(acc2[mp][3]);
        int mA = m0 + ty*8 + mp*2, mB = mA + 1;
        *(float4*)(&Cp[(long)mA*ldc + n0 + tx*4]) =
            make_float4(u0.x+bb.x, u1.x+bb.y, u2.x+bb.z, u3.x+bb.w);
        *(float4*)(&Cp[(long)mB*ldc + n0 + tx*4]) =
            make_float4(u0.y+bb.x, u1.y+bb.y, u2.y+bb.z, u3.y+bb.w);
    }
}

// ============ MK1: gemm1 | copy | transpose | qk(flags) | interp(flags) ============
#define B_G1   128
#define B_CP   (B_G1 + 16)
#define B_TR   (B_CP + 16384)
#define B_QK   (B_TR + 1024)
#define B_END  (B_QK + 4096)

struct InterpS { float sres[256][33]; int soff[32]; float sdx[32], sdy[32]; };

__global__ __launch_bounds__(256)
void mega1_kernel(const float* __restrict__ Z,
                  const float* __restrict__ r,
                  const float* __restrict__ q_z,
                  const float* __restrict__ Q,
                  const float* __restrict__ w2,
                  const float* __restrict__ b2,
                  const float* __restrict__ in_proj_w,
                  const float* __restrict__ in_proj_b,
                  float* __restrict__ outp) {
    __shared__ __align__(16) char smraw[sizeof(InterpS)];
    int bx = blockIdx.x, t = threadIdx.x;

    if (bx < B_G1) {
        // ---- gemm1 (fused query A) -> g_ql; release F_Q + mi ----
        float* As = (float*)smraw;
        float* Bs = As + 16*132;
        int tx = t & 15, ty = t >> 4;
        int m0 = (bx >> 3) * 128, n0 = (bx & 7) * 64;
        int ar = t >> 2, ac = (t & 3) * 4;
        int rowA = m0 + ar, rowB = rowA + 64;
        float qa0 = Q[rowA*3+0], qa1 = Q[rowA*3+1], qa2 = Q[rowA*3+2];
        float qb0 = Q[rowB*3+0], qb1 = Q[rowB*3+1], qb2 = Q[rowB*3+2];

        auto loadA = [&](int row, float q0, float q1, float q2, int k)->float4 {
            if (k < 256) return *(const float4*)(q_z + (long)row*256 + k);
            int h = k - 256;
            const float* w2r = w2 + h*3;
            float4 v;
            v.x = q0*w2r[0] + q1*w2r[1]  + q2*w2r[2]  + b2[h+0];
            v.y = q0*w2r[3] + q1*w2r[4]  + q2*w2r[5]  + b2[h+1];
            v.z = q0*w2r[6] + q1*w2r[7]  + q2*w2r[8]  + b2[h+2];
            v.w = q0*w2r[9] + q1*w2r[10] + q2*w2r[11] + b2[h+3];
            return v;
        };

        float4 ra0 = loadA(rowA, qa0, qa1, qa2, ac);
        float4 ra1 = loadA(rowB, qb0, qb1, qb2, ac);
        float4 rb  = *(const float4*)(in_proj_w + (long)(n0 + ar)*En + ac);

        u64 acc2[4][4] = {};
        for (int k0 = 0; k0 < En; k0 += 16) {
            As[(ac+0)*132+ar]=ra0.x; As[(ac+1)*132+ar]=ra0.y; As[(ac+2)*132+ar]=ra0.z; As[(ac+3)*132+ar]=ra0.w;
            As[(ac+0)*132+ar+64]=ra1.x; As[(ac+1)*132+ar+64]=ra1.y; As[(ac+2)*132+ar+64]=ra1.z; As[(ac+3)*132+ar+64]=ra1.w;
            Bs[(ac+0)*68+ar]=rb.x; Bs[(ac+1)*68+ar]=rb.y; Bs[(ac+2)*68+ar]=rb.z; Bs[(ac+3)*68+ar]=rb.w;
            __syncthreads();
            if (k0 + 16 < En) {
                ra0 = loadA(rowA, qa0, qa1, qa2, k0+16+ac);
                ra1 = loadA(rowB, qb0, qb1, qb2, k0+16+ac);
                rb  = *(const float4*)(in_proj_w + (long)(n0+ar)*En + k0+16+ac);
            }
            #pragma unroll
            for (int k = 0; k < 16; k++) {
                ulonglong2 aA = *(const ulonglong2*)(&As[k*132 + ty*8]);
                ulonglong2 aB = *(const ulonglong2*)(&As[k*132 + ty*8 + 4]);
                float4 bq = *(const float4*)(&Bs[k*68 + tx*4]);
                u64 bs0=splat2(bq.x), bs1=splat2(bq.y), bs2=splat2(bq.z), bs3=splat2(bq.w);
                acc2[0][0]=fma2(aA.x,bs0,acc2[0][0]); acc2[0][1]=fma2(aA.x,bs1,acc2[0][1]);
                acc2[0][2]=fma2(aA.x,bs2,acc2[0][2]); acc2[0][3]=fma2(aA.x,bs3,acc2[0][3]);
                acc2[1][0]=fma2(aA.y,bs0,acc2[1][0]); acc2[1][1]=fma2(aA.y,bs1,acc2[1][1]);
                acc2[1][2]=fma2(aA.y,bs2,acc2[1][2]); acc2[1][3]=fma2(aA.y,bs3,acc2[1][3]);
                acc2[2][0]=fma2(aB.x,bs0,acc2[2][0]); acc2[2][1]=fma2(aB.x,bs1,acc2[2][1]);
                acc2[2][2]=fma2(aB.x,bs2,acc2[2][2]); acc2[2][3]=fma2(aB.x,bs3,acc2[2][3]);
                acc2[3][0]=fma2(aB.y,bs0,acc2[3][0]); acc2[3][1]=fma2(aB.y,bs1,acc2[3][1]);
                acc2[3][2]=fma2(aB.y,bs2,acc2[3][2]); acc2[3][3]=fma2(aB.y,bs3,acc2[3][3]);
            }
            __syncthreads();
        }
        float4 bb = *(const float4*)(in_proj_b + n0 + tx*4);
        #pragma unroll
        for (int mp = 0; mp < 4; mp++) {
            float2 u0=unpack2(acc2[mp][0]), u1=unpack2(acc2[mp][1]);
            float2 u2=unpack2(acc2[mp][2]), u3=unpack2(acc2[mp][3]);
            int mA = m0 + ty*8 + mp*2, mB = mA + 1;
            *(float4*)(&g_ql[(long)mA*En + n0 + tx*4]) =
                make_float4(u0.x+bb.x, u1.x+bb.y, u2.x+bb.z, u3.x+bb.w);
            *(float4*)(&g_ql[(long)mB*En + n0 + tx*4]) =
                make_float4(u0.y+bb.x, u1.y+bb.y, u2.y+bb.z, u3.y+bb.w);
        }
        flag_release(F_Q + (bx >> 3), t);
    } else if (bx < B_CP) {
        // ---- q_z -> outp[:, 0:256) ----
        int r0 = (bx - B_G1) * 128;
        #pragma unroll
        for (int i = 0; i < 32; i++) {
            int idx = i*256 + t;
            int row = r0 + (idx >> 6);
            int c4  = (idx & 63) * 4;
            *(float4*)(outp + (long)row*768 + c4) = *(const float4*)(q_z + (long)row*256 + c4);
        }
    } else if (bx < B_TR) {
        // ---- transpose Z (C, HW*HW) -> Zt; release F_T ----
        float (*tile)[33] = (float(*)[33])smraw;
        int bi = bx - B_CP;
        int xy0 = (bi & 2047) * 32;
        int c0  = (bi >> 11) * 32;
        int tx = t & 31, ty = t >> 5;
        #pragma unroll
        for (int i = 0; i < 32; i += 8)
            tile[ty + i][tx] = Z[(long)(c0 + ty + i)*(HWn*HWn) + xy0 + tx];
        __syncthreads();
        #pragma unroll
        for (int i = 0; i < 32; i += 8)
            g_Zt[(long)(xy0 + ty + i)*Cn + c0 + tx] = tile[tx][ty + i];
        flag_release(F_T, t);
    } else if (bx < B_QK) {
        // ---- qk gemm: waits on gemm1 m-tile ----
        int qi = bx - B_TR;
        int ni = qi & 7, mi = (qi >> 3) & 15, h = qi >> 7;
        flag_acquire(F_Q + mi, 8, t);
        float* As = (float*)smraw;
        gemm128_body(As, As + 16*132, t,
                     g_ql + (long)h*HDn, En,
                     in_proj_w + (long)En*En + (long)h*HDn*En, 1, En,
                     g_qk + (long)h*En, NHn*En, (const float*)0,
                     mi*128, ni*64, HDn);
    } else {
        // ---- bilinear interp: waits on all transpose ----
        flag_acquire(F_T, 16384, t);
        InterpS* S = (InterpS*)smraw;
        int p0 = (bx - B_QK) * 32;
        if (t < 32) {
            float x = r[2*(p0+t)], y = r[2*(p0+t)+1];
            int x1 = (int)x, y1 = (int)y;
            S->soff[t] = (x1*HWn + y1)*Cn;
            S->sdx[t] = x - (float)x1;
            S->sdy[t] = y - (float)y1;
        }
        __syncthreads();
        int wp = t >> 5, l = t & 31;
        #pragma unroll
        for (int pi = 0; pi < 4; pi++) {
            int pl = wp*4 + pi;
            long off = S->soff[pl];
            float dx = S->sdx[pl], dy = S->sdy[pl];
            float omdx = 1.0f - dx, omdy = 1.0f - dy;
            #pragma unroll
            for (int rep = 0; rep < 2; rep++) {
                int c = rep*128 + l*4;
                const float* z11 = g_Zt + off + c;
                float4 a  = *(const float4*)(z11);
                float4 cq = *(const float4*)(z11 + Cn);
                float4 b  = *(const float4*)(z11 + HWn*Cn);
                float4 d  = *(const float4*)(z11 + HWn*Cn + Cn);
                S->sres[c+0][pl] = (a.x*omdx + b.x*dx)*omdy + (cq.x*omdx + d.x*dx)*dy;
                S->sres[c+1][pl] = (a.y*omdx + b.y*dx)*omdy + (cq.y*omdx + d.y*dx)*dy;
                S->sres[c+2][pl] = (a.z*omdx + b.z*dx)*omdy + (cq.z*omdx + d.z*dx)*dy;
                S->sres[c+3][pl] = (a.w*omdx + b.w*dx)*omdy + (cq.w*omdx + d.w*dx)*dy;
            }
        }
        __syncthreads();
        long rowhi = (long)(p0 >> 8);
        int  colb  = p0 & 255;
        #pragma unroll
        for (int i = 0; i < 32; i++) {
            int c = wp*32 + i;
            g_key2[((long)c*512 + rowhi)*256 + colb + l] = S->sres[c][l];
        }
    }
}

// ============ MK2: attn -> v-gemm(flags) -> out-gemm(flags) ============
#define SKS 268
#define SQS 516
#define OFF_SQ   17152
#define OFF_RED  21280
#define OFF_SC   25376
#define OFF_SA   25888
#define OFF_SMAX 26400
#define OFF_SRS  26408
#define OFF_RXY  26416
#define OFF_W1E  26544
#define OFF_W1O  26800
#define OFF_B1S  27056
#define ATTN_FLTS 27312
#define ATTN_SMEM (ATTN_FLTS*4)

#define MK2_V   2048
#define MK2_O   (MK2_V + 128)
#define MK2_END (MK2_O + 128)

__global__ __launch_bounds__(256, 2)
void mega2_kernel(const float* __restrict__ r, const float* __restrict__ w1,
                  const float* __restrict__ b1,
                  const float* __restrict__ in_proj_w,
                  const float* __restrict__ in_proj_b,
                  const float* __restrict__ out_proj_w,
                  const float* __restrict__ out_proj_b,
                  float* __restrict__ outp) {
    extern __shared__ float smf[];
    int bx = blockIdx.x, t = threadIdx.x;

    if (bx >= MK2_O) {
        // ---- out-gemm: waits on v chunk ----
        int oi = bx - MK2_O;
        int ni = oi & 7, mi = oi >> 3;
        flag_acquire(F_V + mi, 8, t);
        gemm128_body(smf, smf + 16*132, t,
                     g_out1, En,
                     out_proj_w, En, 1,
                     outp + 256, 768, out_proj_b,
                     mi*128, ni*64, En);
        return;
    }
    if (bx >= MK2_V) {
        // ---- v-gemm: waits on attn chunk ----
        int vi = bx - MK2_V;
        int mi = vi >> 3, h = vi & 7;
        flag_acquire(F_A + mi, 128, t);
        gemm128_body(smf, smf + 16*132, t,
                     g_ctx + (long)h*En, NHn*En,
                     in_proj_w + (long)2*En*En + (long)h*HDn*En, En, 1,
                     g_out1 + (long)h*HDn, En, in_proj_b + 2*En + h*HDn,
                     mi*128, 0, En);
        flag_release(F_V + mi, t);
        return;
    }

    // ---------------- attention (proven R8 body) ----------------
    float* skey = smf;
    float* sq   = smf + OFF_SQ;
    float* red  = smf + OFF_RED;
    float* sc   = smf + OFF_SC;
    float* sa   = smf + OFF_SA;
    float* smax = smf + OFF_SMAX;
    float* srs  = smf + OFF_SRS;
    float* rxy  = smf + OFF_RXY;
    float* w1e  = smf + OFF_W1E;
    float* w1o  = smf + OFF_W1O;
    float* b1s  = smf + OFF_B1S;

    int b = bx;

    const float* keyb = g_key2 + (long)b * (64*256);
    #pragma unroll
    for (int q = 0; q < 16; q++) {
        int idx = t + 256*q;
        int row = idx >> 6, c4 = (idx & 63) * 4;
        *(float4*)(skey + row*SKS + c4) = *(const float4*)(keyb + row*256 + c4);
    }
    {
        const float4* qsrc = (const float4*)(g_qk + (long)b * 4096);
        #pragma unroll
        for (int q = 0; q < 4; q++) {
            int idx = t + 256*q;
            int row = idx >> 7, c = idx & 127;
            *(float4*)(sq + row*SQS + c*4) = qsrc[row*128 + c];
        }
    }
    if (t < 128) rxy[t] = r[b*128 + t];
    w1e[t] = w1[2*t]; w1o[t] = w1[2*t+1]; b1s[t] = b1[t];
    __syncthreads();

    {
        int s = t >> 5, lane = t & 31;
        int hq = lane >> 4, kq = lane & 15;
        int h0 = hq * 4, jb = s * 32;
        u64 acc2[4][4] = {};
        #pragma unroll
        for (int st = 0; st < 8; st++) {
            int jj = jb + st*4;
            ulonglong2 a0 = *(const ulonglong2*)(sq + (h0+0)*SQS + jj);
            ulonglong2 a1 = *(const ulonglong2*)(sq + (h0+1)*SQS + jj);
            ulonglong2 a2 = *(const ulonglong2*)(sq + (h0+2)*SQS + jj);
            ulonglong2 a3 = *(const ulonglong2*)(sq + (h0+3)*SQS + jj);
            #pragma unroll
            for (int m = 0; m < 4; m++) {
                ulonglong2 bv = *(const ulonglong2*)(skey + (kq + 16*m)*SKS + jj);
                acc2[0][m] = fma2(a0.x, bv.x, acc2[0][m]); acc2[0][m] = fma2(a0.y, bv.y, acc2[0][m]);
                acc2[1][m] = fma2(a1.x, bv.x, acc2[1][m]); acc2[1][m] = fma2(a1.y, bv.y, acc2[1][m]);
                acc2[2][m] = fma2(a2.x, bv.x, acc2[2][m]); acc2[2][m] = fma2(a2.y, bv.y, acc2[2][m]);
                acc2[3][m] = fma2(a3.x, bv.x, acc2[3][m]); acc2[3][m] = fma2(a3.y, bv.y, acc2[3][m]);
            }
        }
        u64 xs[4], ys[4];
        #pragma unroll
        for (int m = 0; m < 4; m++) {
            int k = kq + 16*m;
            xs[m] = splat2(rxy[2*k]);
            ys[m] = splat2(rxy[2*k+1]);
        }
        #pragma unroll
        for (int st = 0; st < 8; st++) {
            int w = jb + st*4, jj = 256 + w;
            ulonglong2 a0 = *(const ulonglong2*)(sq + (h0+0)*SQS + jj);
            ulonglong2 a1 = *(const ulonglong2*)(sq + (h0+1)*SQS + jj);
            ulonglong2 a2 = *(const ulonglong2*)(sq + (h0+2)*SQS + jj);
            ulonglong2 a3 = *(const ulonglong2*)(sq + (h0+3)*SQS + jj);
            ulonglong2 we2 = *(const ulonglong2*)(w1e + w);
            ulonglong2 wo2 = *(const ulonglong2*)(w1o + w);
            ulonglong2 bc2 = *(const ulonglong2*)(b1s + w);
            #pragma unroll
            for (int m = 0; m < 4; m++) {
                u64 bv01 = fma2(xs[m], we2.x, fma2(ys[m], wo2.x, bc2.x));
                u64 bv23 = fma2(xs[m], we2.y, fma2(ys[m], wo2.y, bc2.y));
                acc2[0][m] = fma2(a0.x, bv01, acc2[0][m]); acc2[0][m] = fma2(a0.y, bv23, acc2[0][m]);
                acc2[1][m] = fma2(a1.x, bv01, acc2[1][m]); acc2[1][m] = fma2(a1.y, bv23, acc2[1][m]);
                acc2[2][m] = fma2(a2.x, bv01, acc2[2][m]); acc2[2][m] = fma2(a2.y, bv23, acc2[2][m]);
                acc2[3][m] = fma2(a3.x, bv01, acc2[3][m]); acc2[3][m] = fma2(a3.y, bv23, acc2[3][m]);
            }
        }
        #pragma unroll
        for (int hi = 0; hi < 4; hi++)
            #pragma unroll
            for (int m = 0; m < 4; m++) {
                float2 u = unpack2(acc2[hi][m]);
                red[s*512 + (h0+hi)*64 + m*16 + kq] = u.x + u.y;
            }
    }
    __syncthreads();
    #pragma unroll
    for (int e0 = 0; e0 < 2; e0++) {
        int e = t + e0*256;
        float v = 0.f;
        #pragma unroll
        for (int s2 = 0; s2 < 8; s2++) v += red[s2*512 + e];
        sc[e] = v * 0.125f;
    }
    __syncthreads();

    if (t < 32) {
        int h = t >> 2, seg = t & 3;
        const float* p = sc + h*64 + seg*16;
        float mx = p[0];
        #pragma unroll
        for (int i = 1; i < 16; i++) mx = fmaxf(mx, p[i]);
        mx = fmaxf(mx, __shfl_xor_sync(0xffffffffu, mx, 1));
        mx = fmaxf(mx, __shfl_xor_sync(0xffffffffu, mx, 2));
        float sm = 0.f;
        #pragma unroll
        for (int i = 0; i < 16; i++) sm += __expf(p[i] - mx);
        sm += __shfl_xor_sync(0xffffffffu, sm, 1);
        sm += __shfl_xor_sync(0xffffffffu, sm, 2);
        if (seg == 0) { smax[h] = mx; srs[h] = 1.0f / sm; }
    }
    __syncthreads();
    sa[t]     = __expf(sc[t]     - smax[t >> 6])       * srs[t >> 6];
    sa[t+256] = __expf(sc[t+256] - smax[(t+256) >> 6]) * srs[(t+256) >> 6];
    __syncthreads();

    {
        int hq = t >> 7, jq = t & 127;
        int h0 = hq * 4, j0 = jq * 4;
        const float* sa0 = sa + (h0+0)*64;
        const float* sa1 = sa + (h0+1)*64;
        const float* sa2 = sa + (h0+2)*64;
        const float* sa3 = sa + (h0+3)*64;
        u64 acc2[4][2] = {};
        if (j0 < 256) {
            #pragma unroll
            for (int k4 = 0; k4 < 64; k4 += 4) {
                float4 av0 = *(const float4*)(sa0 + k4);
                float4 av1 = *(const float4*)(sa1 + k4);
                float4 av2 = *(const float4*)(sa2 + k4);
                float4 av3 = *(const float4*)(sa3 + k4);
                float a0r[4] = {av0.x, av0.y, av0.z, av0.w};
                float a1r[4] = {av1.x, av1.y, av1.z, av1.w};
                float a2r[4] = {av2.x, av2.y, av2.z, av2.w};
                float a3r[4] = {av3.x, av3.y, av3.z, av3.w};
                #pragma unroll
                for (int kk = 0; kk < 4; kk++) {
                    ulonglong2 bv = *(const ulonglong2*)(skey + (k4+kk)*SKS + j0);
                    u64 s0 = splat2(a0r[kk]), s1 = splat2(a1r[kk]);
                    u64 s2 = splat2(a2r[kk]), s3 = splat2(a3r[kk]);
                    acc2[0][0]=fma2(s0,bv.x,acc2[0][0]); acc2[0][1]=fma2(s0,bv.y,acc2[0][1]);
                    acc2[1][0]=fma2(s1,bv.x,acc2[1][0]); acc2[1][1]=fma2(s1,bv.y,acc2[1][1]);
                    acc2[2][0]=fma2(s2,bv.x,acc2[2][0]); acc2[2][1]=fma2(s2,bv.y,acc2[2][1]);
                    acc2[3][0]=fma2(s3,bv.x,acc2[3][0]); acc2[3][1]=fma2(s3,bv.y,acc2[3][1]);
                }
            }
        } else {
            int w = j0 - 256;
            ulonglong2 we2 = *(const ulonglong2*)(w1e + w);
            ulonglong2 wo2 = *(const ulonglong2*)(w1o + w);
            ulonglong2 bc2 = *(const ulonglong2*)(b1s + w);
            #pragma unroll
            for (int k4 = 0; k4 < 64; k4 += 4) {
                float4 av0 = *(const float4*)(sa0 + k4);
                float4 av1 = *(const float4*)(sa1 + k4);
                float4 av2 = *(const float4*)(sa2 + k4);
                float4 av3 = *(const float4*)(sa3 + k4);
                float a0r[4] = {av0.x, av0.y, av0.z, av0.w};
                float a1r[4] = {av1.x, av1.y, av1.z, av1.w};
                float a2r[4] = {av2.x, av2.y, av2.z, av2.w};
                float a3r[4] = {av3.x, av3.y, av3.z, av3.w};
                #pragma unroll
                for (int kk = 0; kk < 4; kk++) {
                    int k = k4 + kk;
                    u64 xs = splat2(rxy[2*k]), ys = splat2(rxy[2*k+1]);
                    u64 bv01 = fma2(xs, we2.x, fma2(ys, wo2.x, bc2.x));
                    u64 bv23 = fma2(xs, we2.y, fma2(ys, wo2.y, bc2.y));
                    u64 s0 = splat2(a0r[kk]), s1 = splat2(a1r[kk]);
                    u64 s2 = splat2(a2r[kk]), s3 = splat2(a3r[kk]);
                    acc2[0][0]=fma2(s0,bv01,acc2[0][0]); acc2[0][1]=fma2(s0,bv23,acc2[0][1]);
                    acc2[1][0]=fma2(s1,bv01,acc2[1][0]); acc2[1][1]=fma2(s1,bv23,acc2[1][1]);
                    acc2[2][0]=fma2(s2,bv01,acc2[2][0]); acc2[2][1]=fma2(s2,bv23,acc2[2][1]);
                    acc2[3][0]=fma2(s3,bv01,acc2[3][0]); acc2[3][1]=fma2(s3,bv23,acc2[3][1]);
                }
            }
        }
        float* ctxb = g_ctx + (long)b * 4096;
        #pragma unroll
        for (int hi = 0; hi < 4; hi++) {
            float2 u0 = unpack2(acc2[hi][0]);
            float2 u1 = unpack2(acc2[hi][1]);
            *(float4*)(ctxb + (h0+hi)*512 + j0) = make_float4(u0.x, u0.y, u1.x, u1.y);
        }
    }
    flag_release(F_A + (b >> 7), t);
}

// ---------------- host launcher ----------------
extern "C" void kernel_launch(void* const* d_in, const int* in_sizes, int n_in,
                              void* d_out, int out_size) {
    const float* Z          = (const float*)d_in[0];
    const float* Q          = (const float*)d_in[1];
    const float* q_z        = (const float*)d_in[2];
    const float* r          = (const float*)d_in[3];
    const float* w1         = (const float*)d_in[4];
    const float* b1         = (const float*)d_in[5];
    const float* w2         = (const float*)d_in[6];
    const float* b2         = (const float*)d_in[7];
    const float* in_proj_w  = (const float*)d_in[8];
    const float* in_proj_b  = (const float*)d_in[9];
    const float* out_proj_w = (const float*)d_in[10];
    const float* out_proj_b = (const float*)d_in[11];
    float* outp = (float*)d_out;

    int* pFlags;
    cudaGetSymbolAddress((void**)&pFlags, g_flags);
    cudaMemsetAsync(pFlags, 0, 64 * sizeof(int));

    cudaFuncSetAttribute(mega2_kernel,
                         cudaFuncAttributeMaxDynamicSharedMemorySize, ATTN_SMEM);

    // MK1: gemm1 | qz-copy | transpose | qk(flag-dep) | interp(flag-dep)
    mega1_kernel<<<B_END, 256>>>(Z, r, q_z, Q, w2, b2, in_proj_w, in_proj_b, outp);

    // MK2: attn -> v-gemm(flag-dep) -> out-gemm(flag-dep)
    mega2_kernel<<<MK2_END, 256, ATTN_SMEM>>>(r, w1, b1, in_proj_w, in_proj_b,
                                              out_proj_w, out_proj_b, outp);
}

// round 13
// speedup vs baseline: 1.0878x; 1.0788x over previous
#include <cuda_runtime.h>
#include <math.h>
#include <stdint.h>

#define SQn   2048
#define SKn   64
#define Cn    256
#define HWn   256
#define En    512
#define NPn   (SQn*SKn)
#define NHn   8
#define HDn   64

typedef unsigned long long u64;

__device__ __forceinline__ u64 fma2(u64 a, u64 b, u64 c) {
    u64 d;
    asm("fma.rn.f32x2 %0, %1, %2, %3;" : "=l"(d) : "l"(a), "l"(b), "l"(c));
    return d;
}
__device__ __forceinline__ u64 pack2(float lo, float hi) {
    u64 v;
    asm("mov.b64 %0, {%1, %2};" : "=l"(v) : "f"(lo), "f"(hi));
    return v;
}
__device__ __forceinline__ float2 unpack2(u64 v) {
    float lo, hi;
    asm("mov.b64 {%0, %1}, %2;" : "=f"(lo), "=f"(hi) : "l"(v));
    return make_float2(lo, hi);
}
__device__ __forceinline__ u64 splat2(float a) { return pack2(a, a); }

// ---------------- scratch ----------------
__device__ float g_Zt[(size_t)Cn*HWn*HWn];
__device__ float g_key2[(size_t)NPn*256];
__device__ float g_ql[(size_t)SQn*En];
__device__ float g_qk[(size_t)SQn*NHn*En];
__device__ float g_ctx[(size_t)SQn*NHn*En];
__device__ float g_out1[(size_t)SQn*En];
__device__ int   g_flags[32];    // [0..15]: v-gemm m-chunk counts (target 8)

__device__ __forceinline__ void flag_release(int idx, int t) {
    __syncthreads();
    __threadfence();
    if (t == 0) atomicAdd(&g_flags[idx], 1);
}
__device__ __forceinline__ void flag_acquire(int idx, int target, int t) {
    if (t == 0) {
        while (atomicAdd(&g_flags[idx], 0) < target) { }
        __threadfence();
    }
    __syncthreads();
}

// ---------------- 1) transpose Z (C, HW*HW) -> Zt (HW*HW, C) ----------------
__global__ void transpose_kernel(const float* __restrict__ Z) {
    __shared__ float tile[32][33];
    int xy0 = blockIdx.x * 32;
    int c0  = blockIdx.y * 32;
    int tx = threadIdx.x, ty = threadIdx.y;   // 32 x 8
    #pragma unroll
    for (int i = 0; i < 32; i += 8)
        tile[ty + i][tx] = Z[(long)(c0 + ty + i) * (HWn*HWn) + xy0 + tx];
    __syncthreads();
    #pragma unroll
    for (int i = 0; i < 32; i += 8)
        g_Zt[(long)(xy0 + ty + i) * Cn + c0 + tx] = tile[tx][ty + i];
}

// ---------------- 2) FAT kernel: gemm1(query fused) | qz->out copy | interp ----------------
#define FAT_GEMM_BLKS 128
#define FAT_COPY_BLKS 16
#define FAT_INTERP_OFF (FAT_GEMM_BLKS + FAT_COPY_BLKS)

struct InterpS { float sres[256][33]; int soff[32]; float sdx[32], sdy[32]; };
struct GemmS   { float As[16][132]; float Bs[16][68]; };

__global__ __launch_bounds__(256)
void fat_kernel(const float* __restrict__ r,
                const float* __restrict__ q_z,
                const float* __restrict__ Q,
                const float* __restrict__ w2,
                const float* __restrict__ b2,
                const float* __restrict__ in_proj_w,
                const float* __restrict__ in_proj_b,
                float* __restrict__ outp) {
    __shared__ __align__(16) char smraw[sizeof(InterpS)];
    int bx = blockIdx.x;
    int t = threadIdx.x;

    if (bx < FAT_GEMM_BLKS) {
        GemmS* S = (GemmS*)smraw;
        int tx = t & 15, ty = t >> 4;
        int m0 = (bx >> 3) * 128;
        int n0 = (bx & 7) * 64;
        int ar = t >> 2, ac = (t & 3) * 4;

        int rowA = m0 + ar, rowB = m0 + ar + 64;
        float qa0 = Q[rowA*3+0], qa1 = Q[rowA*3+1], qa2 = Q[rowA*3+2];
        float qb0 = Q[rowB*3+0], qb1 = Q[rowB*3+1], qb2 = Q[rowB*3+2];

        const float* B = in_proj_w;

        auto loadA = [&](int row, float q0, float q1, float q2, int k)->float4 {
            if (k < 256) {
                return *(const float4*)(q_z + (long)row*256 + k);
            } else {
                int h = k - 256;
                const float* w2r = w2 + h*3;
                float4 v;
                v.x = q0*w2r[0] + q1*w2r[1]  + q2*w2r[2]  + b2[h+0];
                v.y = q0*w2r[3] + q1*w2r[4]  + q2*w2r[5]  + b2[h+1];
                v.z = q0*w2r[6] + q1*w2r[7]  + q2*w2r[8]  + b2[h+2];
                v.w = q0*w2r[9] + q1*w2r[10] + q2*w2r[11] + b2[h+3];
                return v;
            }
        };

        float4 ra0 = loadA(rowA, qa0, qa1, qa2, ac);
        float4 ra1 = loadA(rowB, qb0, qb1, qb2, ac);
        float4 rb  = *(const float4*)(B + (long)(n0 + ar) * En + ac);

        u64 acc2[4][4] = {};
        for (int k0 = 0; k0 < En; k0 += 16) {
            S->As[ac+0][ar]    = ra0.x; S->As[ac+1][ar]    = ra0.y; S->As[ac+2][ar]    = ra0.z; S->As[ac+3][ar]    = ra0.w;
            S->As[ac+0][ar+64] = ra1.x; S->As[ac+1][ar+64] = ra1.y; S->As[ac+2][ar+64] = ra1.z; S->As[ac+3][ar+64] = ra1.w;
            S->Bs[ac+0][ar] = rb.x; S->Bs[ac+1][ar] = rb.y; S->Bs[ac+2][ar] = rb.z; S->Bs[ac+3][ar] = rb.w;
            __syncthreads();
            if (k0 + 16 < En) {
                ra0 = loadA(rowA, qa0, qa1, qa2, k0 + 16 + ac);
                ra1 = loadA(rowB, qb0, qb1, qb2, k0 + 16 + ac);
                rb  = *(const float4*)(B + (long)(n0 + ar) * En + k0 + 16 + ac);
            }
            #pragma unroll
            for (int k = 0; k < 16; k++) {
                ulonglong2 aA = *(const ulonglong2*)(&S->As[k][ty*8]);
                ulonglong2 aB = *(const ulonglong2*)(&S->As[k][ty*8+4]);
                float4 bq = *(const float4*)(&S->Bs[k][tx*4]);
                u64 ap0 = aA.x, ap1 = aA.y, ap2 = aB.x, ap3 = aB.y;
                u64 bs0 = splat2(bq.x), bs1 = splat2(bq.y), bs2 = splat2(bq.z), bs3 = splat2(bq.w);
                acc2[0][0]=fma2(ap0,bs0,acc2[0][0]); acc2[0][1]=fma2(ap0,bs1,acc2[0][1]);
                acc2[0][2]=fma2(ap0,bs2,acc2[0][2]); acc2[0][3]=fma2(ap0,bs3,acc2[0][3]);
                acc2[1][0]=fma2(ap1,bs0,acc2[1][0]); acc2[1][1]=fma2(ap1,bs1,acc2[1][1]);
                acc2[1][2]=fma2(ap1,bs2,acc2[1][2]); acc2[1][3]=fma2(ap1,bs3,acc2[1][3]);
                acc2[2][0]=fma2(ap2,bs0,acc2[2][0]); acc2[2][1]=fma2(ap2,bs1,acc2[2][1]);
                acc2[2][2]=fma2(ap2,bs2,acc2[2][2]); acc2[2][3]=fma2(ap2,bs3,acc2[2][3]);
                acc2[3][0]=fma2(ap3,bs0,acc2[3][0]); acc2[3][1]=fma2(ap3,bs1,acc2[3][1]);
                acc2[3][2]=fma2(ap3,bs2,acc2[3][2]); acc2[3][3]=fma2(ap3,bs3,acc2[3][3]);
            }
            __syncthreads();
        }
        float4 bb = *(const float4*)(in_proj_b + n0 + tx*4);
        #pragma unroll
        for (int mp = 0; mp < 4; mp++) {
            float2 u0 = unpack2(acc2[mp][0]);
            float2 u1 = unpack2(acc2[mp][1]);
            float2 u2 = unpack2(acc2[mp][2]);
            float2 u3 = unpack2(acc2[mp][3]);
            int mA = m0 + ty*8 + mp*2, mB = mA + 1;
            *(float4*)(&g_ql[(long)mA * En + n0 + tx*4]) =
                make_float4(u0.x+bb.x, u1.x+bb.y, u2.x+bb.z, u3.x+bb.w);
            *(float4*)(&g_ql[(long)mB * En + n0 + tx*4]) =
                make_float4(u0.y+bb.x, u1.y+bb.y, u2.y+bb.z, u3.y+bb.w);
        }
    } else if (bx < FAT_INTERP_OFF) {
        int r0 = (bx - FAT_GEMM_BLKS) * 128;
        #pragma unroll
        for (int i = 0; i < 32; i++) {
            int idx = i * 256 + t;
            int row = r0 + (idx >> 6);
            int c4  = (idx & 63) * 4;
            float4 v = *(const float4*)(q_z + (long)row*256 + c4);
            *(float4*)(outp + (long)row*768 + c4) = v;
        }
    } else {
        InterpS* S = (InterpS*)smraw;
        int p0 = (bx - FAT_INTERP_OFF) * 32;
        if (t < 32) {
            float x = r[2*(p0+t)], y = r[2*(p0+t)+1];
            int x1 = (int)x, y1 = (int)y;
            S->soff[t] = (x1*HWn + y1)*Cn;
            S->sdx[t] = x - (float)x1;
            S->sdy[t] = y - (float)y1;
        }
        __syncthreads();
        int wp = t >> 5, l = t & 31;
        #pragma unroll
        for (int pi = 0; pi < 4; pi++) {
            int pl = wp*4 + pi;
            long off = S->soff[pl];
            float dx = S->sdx[pl], dy = S->sdy[pl];
            float omdx = 1.0f - dx, omdy = 1.0f - dy;
            #pragma unroll
            for (int rep = 0; rep < 2; rep++) {
                int c = rep*128 + l*4;
                const float* z11 = g_Zt + off + c;
                float4 a  = *(const float4*)(z11);
                float4 cq = *(const float4*)(z11 + Cn);
                float4 b  = *(const float4*)(z11 + HWn*Cn);
                float4 d  = *(const float4*)(z11 + HWn*Cn + Cn);
                S->sres[c+0][pl] = (a.x*omdx + b.x*dx)*omdy + (cq.x*omdx + d.x*dx)*dy;
                S->sres[c+1][pl] = (a.y*omdx + b.y*dx)*omdy + (cq.y*omdx + d.y*dx)*dy;
                S->sres[c+2][pl] = (a.z*omdx + b.z*dx)*omdy + (cq.z*omdx + d.z*dx)*dy;
                S->sres[c+3][pl] = (a.w*omdx + b.w*dx)*omdy + (cq.w*omdx + d.w*dx)*dy;
            }
        }
        __syncthreads();
        long rowhi = (long)(p0 >> 8);
        int  colb  = p0 & 255;
        #pragma unroll
        for (int i = 0; i < 32; i++) {
            int c = wp*32 + i;
            g_key2[((long)c*512 + rowhi)*256 + colb + l] = S->sres[c][l];
        }
    }
}

// ============ proven 128x64 f32x2 GEMM body ============
__device__ __forceinline__ void gemm128_body(
    float* As, float* Bs, int t,
    const float* __restrict__ A, int lda,
    const float* __restrict__ B, int ldbn, int ldbk,
    float* __restrict__ Cp, int ldc, const float* __restrict__ bias,
    int m0, int n0, int K)
{
    int tx = t & 15, ty = t >> 4;
    int ar = t >> 2, ac = (t & 3) * 4;
    const bool bvec = (ldbk == 1);
    const float* Abase = A + (long)(m0 + ar) * lda + ac;

    float4 ra0 = *(const float4*)(Abase);
    float4 ra1 = *(const float4*)(Abase + (long)64 * lda);
    float4 rb; float rbs[4];
    if (bvec) {
        rb = *(const float4*)(B + (long)(n0 + ar) * ldbn + ac);
    } else {
        #pragma unroll
        for (int q = 0; q < 4; q++) {
            int idx = t + 256*q; int nn = idx & 63, kk = idx >> 6;
            rbs[q] = B[(long)(n0 + nn) + (long)kk * ldbk];
        }
    }

    u64 acc2[4][4] = {};
    for (int k0 = 0; k0 < K; k0 += 16) {
        As[(ac+0)*132+ar]=ra0.x; As[(ac+1)*132+ar]=ra0.y; As[(ac+2)*132+ar]=ra0.z; As[(ac+3)*132+ar]=ra0.w;
        As[(ac+0)*132+ar+64]=ra1.x; As[(ac+1)*132+ar+64]=ra1.y; As[(ac+2)*132+ar+64]=ra1.z; As[(ac+3)*132+ar+64]=ra1.w;
        if (bvec) {
            Bs[(ac+0)*68+ar]=rb.x; Bs[(ac+1)*68+ar]=rb.y; Bs[(ac+2)*68+ar]=rb.z; Bs[(ac+3)*68+ar]=rb.w;
        } else {
            #pragma unroll
            for (int q = 0; q < 4; q++) {
                int idx = t + 256*q; int nn = idx & 63, kk = idx >> 6;
                Bs[kk*68+nn] = rbs[q];
            }
        }
        __syncthreads();
        if (k0 + 16 < K) {
            const float* An = Abase + k0 + 16;
            ra0 = *(const float4*)(An);
            ra1 = *(const float4*)(An + (long)64 * lda);
            if (bvec) {
                rb = *(const float4*)(B + (long)(n0 + ar) * ldbn + k0 + 16 + ac);
            } else {
                #pragma unroll
                for (int q = 0; q < 4; q++) {
                    int idx = t + 256*q; int nn = idx & 63, kk = idx >> 6;
                    rbs[q] = B[(long)(n0 + nn) + (long)(k0 + 16 + kk) * ldbk];
                }
            }
        }
        #pragma unroll
        for (int k = 0; k < 16; k++) {
            ulonglong2 aA = *(const ulonglong2*)(&As[k*132 + ty*8]);
            ulonglong2 aB = *(const ulonglong2*)(&As[k*132 + ty*8 + 4]);
            float4 bq = *(const float4*)(&Bs[k*68 + tx*4]);
            u64 bs0=splat2(bq.x), bs1=splat2(bq.y), bs2=splat2(bq.z), bs3=splat2(bq.w);
            acc2[0][0]=fma2(aA.x,bs0,acc2[0][0]); acc2[0][1]=fma2(aA.x,bs1,acc2[0][1]);
            acc2[0][2]=fma2(aA.x,bs2,acc2[0][2]); acc2[0][3]=fma2(aA.x,bs3,acc2[0][3]);
            acc2[1][0]=fma2(aA.y,bs0,acc2[1][0]); acc2[1][1]=fma2(aA.y,bs1,acc2[1][1]);
            acc2[1][2]=fma2(aA.y,bs2,acc2[1][2]); acc2[1][3]=fma2(aA.y,bs3,acc2[1][3]);
            acc2[2][0]=fma2(aB.x,bs0,acc2[2][0]); acc2[2][1]=fma2(aB.x,bs1,acc2[2][1]);
            acc2[2][2]=fma2(aB.x,bs2,acc2[2][2]); acc2[2][3]=fma2(aB.x,bs3,acc2[2][3]);
            acc2[3][0]=fma2(aB.y,bs0,acc2[3][0]); acc2[3][1]=fma2(aB.y,bs1,acc2[3][1]);
            acc2[3][2]=fma2(aB.y,bs2,acc2[3][2]); acc2[3][3]=fma2(aB.y,bs3,acc2[3][3]);
        }
        __syncthreads();
    }
    float4 bb = make_float4(0.f,0.f,0.f,0.f);
    if (bias) bb = *(const float4*)(bias + n0 + tx*4);
    #pragma unroll
    for (int mp = 0; mp < 4; mp++) {
        float2 u0=unpack2(acc2[mp][0]), u1=unpack2(acc2[mp][1]);
        float2 u2=unpack2(acc2[mp][2]), u3=unpack2(acc2[mp][3]);
        int mA = m0 + ty*8 + mp*2, mB = mA + 1;
        *(float4*)(&Cp[(long)mA*ldc + n0 + tx*4]) =
            make_float4(u0.x+bb.x, u1.x+bb.y, u2.x+bb.z, u3.x+bb.w);
        *(float4*)(&Cp[(long)mB*ldc + n0 + tx*4]) =
            make_float4(u0.y+bb.x, u1.y+bb.y, u2.y+bb.z, u3.y+bb.w);
    }
}

// ---------------- 3) qk gemm (standalone, 128x64, proven) ----------------
__global__ __launch_bounds__(256)
void qk_kernel(const float* __restrict__ in_proj_w) {
    __shared__ float sm[16*132 + 16*68];
    int h = blockIdx.z;
    gemm128_body(sm, sm + 16*132, threadIdx.x,
                 g_ql + (long)h*HDn, En,
                 in_proj_w + (long)En*En + (long)h*HDn*En, 1, En,
                 g_qk + (long)h*En, NHn*En, (const float*)0,
                 blockIdx.y*128, blockIdx.x*64, HDn);
}

// ---------------- 5) v-gemm + out-gemm fused with flags ----------------
__global__ __launch_bounds__(256)
void vout_kernel(const float* __restrict__ in_proj_w,
                 const float* __restrict__ in_proj_b,
                 const float* __restrict__ out_proj_w,
                 const float* __restrict__ out_proj_b,
                 float* __restrict__ outp) {
    __shared__ float sm[16*132 + 16*68];
    int bx = blockIdx.x, t = threadIdx.x;
    if (bx < 128) {
        // v: out1[m][h*64+:] = ctx[m][h][:] . Wv_h + bv   (16 m-chunks x 8 heads)
        int mi = bx >> 3, h = bx & 7;
        gemm128_body(sm, sm + 16*132, t,
                     g_ctx + (long)h*En, NHn*En,
                     in_proj_w + (long)2*En*En + (long)h*HDn*En, En, 1,
                     g_out1 + (long)h*HDn, En, in_proj_b + 2*En + h*HDn,
                     mi*128, 0, En);
        flag_release(mi, t);
    } else {
        // out: outp[:,256:768] = out1 @ Wo^T + bo  (16 m x 8 n)
        int oi = bx - 128;
        int ni = oi & 7, mi = oi >> 3;
        flag_acquire(mi, 8, t);
        gemm128_body(sm, sm + 16*132, t,
                     g_out1, En,
                     out_proj_w, En, 1,
                     outp + 256, 768, out_proj_b,
                     mi*128, ni*64, En);
    }
}

// ---------------- 4) fused attention (R8, unchanged) ----------------
#define SKS 268
#define SQS 516
#define OFF_SQ   17152
#define OFF_RED  21280
#define OFF_SC   25376
#define OFF_SA   25888
#define OFF_SMAX 26400
#define OFF_SRS  26408
#define OFF_RXY  26416
#define OFF_W1E  26544
#define OFF_W1O  26800
#define OFF_B1S  27056
#define ATTN_FLTS 27312
#define ATTN_SMEM (ATTN_FLTS*4)

__global__ __launch_bounds__(256, 2)
void attn_kernel(const float* __restrict__ r, const float* __restrict__ w1,
                 const float* __restrict__ b1) {
    extern __shared__ float smf[];
    float* skey = smf;
    float* sq   = smf + OFF_SQ;
    float* red  = smf + OFF_RED;
    float* sc   = smf + OFF_SC;
    float* sa   = smf + OFF_SA;
    float* smax = smf + OFF_SMAX;
    float* srs  = smf + OFF_SRS;
    float* rxy  = smf + OFF_RXY;
    float* w1e  = smf + OFF_W1E;
    float* w1o  = smf + OFF_W1O;
    float* b1s  = smf + OFF_B1S;

    int b = blockIdx.x, t = threadIdx.x;

    const float* keyb = g_key2 + (long)b * (64*256);
    #pragma unroll
    for (int q = 0; q < 16; q++) {
        int idx = t + 256*q;
        int row = idx >> 6, c4 = (idx & 63) * 4;
        *(float4*)(skey + row*SKS + c4) = *(const float4*)(keyb + row*256 + c4);
    }
    {
        const float4* qsrc = (const float4*)(g_qk + (long)b * 4096);
        #pragma unroll
        for (int q = 0; q < 4; q++) {
            int idx = t + 256*q;
            int row = idx >> 7, c = idx & 127;
            *(float4*)(sq + row*SQS + c*4) = qsrc[row*128 + c];
        }
    }
    if (t < 128) rxy[t] = r[b*128 + t];
    w1e[t] = w1[2*t]; w1o[t] = w1[2*t+1]; b1s[t] = b1[t];
    __syncthreads();

    {
        int s = t >> 5, lane = t & 31;
        int hq = lane >> 4, kq = lane & 15;
        int h0 = hq * 4, jb = s * 32;
        u64 acc2[4][4] = {};
        #pragma unroll
        for (int st = 0; st < 8; st++) {
            int jj = jb + st*4;
            ulonglong2 a0 = *(const ulonglong2*)(sq + (h0+0)*SQS + jj);
            ulonglong2 a1 = *(const ulonglong2*)(sq + (h0+1)*SQS + jj);
            ulonglong2 a2 = *(const ulonglong2*)(sq + (h0+2)*SQS + jj);
            ulonglong2 a3 = *(const ulonglong2*)(sq + (h0+3)*SQS + jj);
            #pragma unroll
            for (int m = 0; m < 4; m++) {
                ulonglong2 bv = *(const ulonglong2*)(skey + (kq + 16*m)*SKS + jj);
                acc2[0][m] = fma2(a0.x, bv.x, acc2[0][m]); acc2[0][m] = fma2(a0.y, bv.y, acc2[0][m]);
                acc2[1][m] = fma2(a1.x, bv.x, acc2[1][m]); acc2[1][m] = fma2(a1.y, bv.y, acc2[1][m]);
                acc2[2][m] = fma2(a2.x, bv.x, acc2[2][m]); acc2[2][m] = fma2(a2.y, bv.y, acc2[2][m]);
                acc2[3][m] = fma2(a3.x, bv.x, acc2[3][m]); acc2[3][m] = fma2(a3.y, bv.y, acc2[3][m]);
            }
        }
        u64 xs[4], ys[4];
        #pragma unroll
        for (int m = 0; m < 4; m++) {
            int k = kq + 16*m;
            xs[m] = splat2(rxy[2*k]);
            ys[m] = splat2(rxy[2*k+1]);
        }
        #pragma unroll
        for (int st = 0; st < 8; st++) {
            int w = jb + st*4, jj = 256 + w;
            ulonglong2 a0 = *(const ulonglong2*)(sq + (h0+0)*SQS + jj);
            ulonglong2 a1 = *(const ulonglong2*)(sq + (h0+1)*SQS + jj);
            ulonglong2 a2 = *(const ulonglong2*)(sq + (h0+2)*SQS + jj);
            ulonglong2 a3 = *(const ulonglong2*)(sq + (h0+3)*SQS + jj);
            ulonglong2 we2 = *(const ulonglong2*)(w1e + w);
            ulonglong2 wo2 = *(const ulonglong2*)(w1o + w);
            ulonglong2 bc2 = *(const ulonglong2*)(b1s + w);
            #pragma unroll
            for (int m = 0; m < 4; m++) {
                u64 bv01 = fma2(xs[m], we2.x, fma2(ys[m], wo2.x, bc2.x));
                u64 bv23 = fma2(xs[m], we2.y, fma2(ys[m], wo2.y, bc2.y));
                acc2[0][m] = fma2(a0.x, bv01, acc2[0][m]); acc2[0][m] = fma2(a0.y, bv23, acc2[0][m]);
                acc2[1][m] = fma2(a1.x, bv01, acc2[1][m]); acc2[1][m] = fma2(a1.y, bv23, acc2[1][m]);
                acc2[2][m] = fma2(a2.x, bv01, acc2[2][m]); acc2[2][m] = fma2(a2.y, bv23, acc2[2][m]);
                acc2[3][m] = fma2(a3.x, bv01, acc2[3][m]); acc2[3][m] = fma2(a3.y, bv23, acc2[3][m]);
            }
        }
        #pragma unroll
        for (int hi = 0; hi < 4; hi++)
            #pragma unroll
            for (int m = 0; m < 4; m++) {
                float2 u = unpack2(acc2[hi][m]);
                red[s*512 + (h0+hi)*64 + m*16 + kq] = u.x + u.y;
            }
    }
    __syncthreads();
    #pragma unroll
    for (int e0 = 0; e0 < 2; e0++) {
        int e = t + e0*256;
        float v = 0.f;
        #pragma unroll
        for (int s2 = 0; s2 < 8; s2++) v += red[s2*512 + e];
        sc[e] = v * 0.125f;
    }
    __syncthreads();

    if (t < 32) {
        int h = t >> 2, seg = t & 3;
        const float* p = sc + h*64 + seg*16;
        float mx = p[0];
        #pragma unroll
        for (int i = 1; i < 16; i++) mx = fmaxf(mx, p[i]);
        mx = fmaxf(mx, __shfl_xor_sync(0xffffffffu, mx, 1));
        mx = fmaxf(mx, __shfl_xor_sync(0xffffffffu, mx, 2));
        float sm = 0.f;
        #pragma unroll
        for (int i = 0; i < 16; i++) sm += __expf(p[i] - mx);
        sm += __shfl_xor_sync(0xffffffffu, sm, 1);
        sm += __shfl_xor_sync(0xffffffffu, sm, 2);
        if (seg == 0) { smax[h] = mx; srs[h] = 1.0f / sm; }
    }
    __syncthreads();
    sa[t]     = __expf(sc[t]     - smax[t >> 6])       * srs[t >> 6];
    sa[t+256] = __expf(sc[t+256] - smax[(t+256) >> 6]) * srs[(t+256) >> 6];
    __syncthreads();

    {
        int hq = t >> 7, jq = t & 127;
        int h0 = hq * 4, j0 = jq * 4;
        const float* sa0 = sa + (h0+0)*64;
        const float* sa1 = sa + (h0+1)*64;
        const float* sa2 = sa + (h0+2)*64;
        const float* sa3 = sa + (h0+3)*64;
        u64 acc2[4][2] = {};
        if (j0 < 256) {
            #pragma unroll
            for (int k4 = 0; k4 < 64; k4 += 4) {
                float4 av0 = *(const float4*)(sa0 + k4);
                float4 av1 = *(const float4*)(sa1 + k4);
                float4 av2 = *(const float4*)(sa2 + k4);
                float4 av3 = *(const float4*)(sa3 + k4);
                float a0r[4] = {av0.x, av0.y, av0.z, av0.w};
                float a1r[4] = {av1.x, av1.y, av1.z, av1.w};
                float a2r[4] = {av2.x, av2.y, av2.z, av2.w};
                float a3r[4] = {av3.x, av3.y, av3.z, av3.w};
                #pragma unroll
                for (int kk = 0; kk < 4; kk++) {
                    ulonglong2 bv = *(const ulonglong2*)(skey + (k4+kk)*SKS + j0);
                    u64 s0 = splat2(a0r[kk]), s1 = splat2(a1r[kk]);
                    u64 s2 = splat2(a2r[kk]), s3 = splat2(a3r[kk]);
                    acc2[0][0]=fma2(s0,bv.x,acc2[0][0]); acc2[0][1]=fma2(s0,bv.y,acc2[0][1]);
                    acc2[1][0]=fma2(s1,bv.x,acc2[1][0]); acc2[1][1]=fma2(s1,bv.y,acc2[1][1]);
                    acc2[2][0]=fma2(s2,bv.x,acc2[2][0]); acc2[2][1]=fma2(s2,bv.y,acc2[2][1]);
                    acc2[3][0]=fma2(s3,bv.x,acc2[3][0]); acc2[3][1]=fma2(s3,bv.y,acc2[3][1]);
                }
            }
        } else {
            int w = j0 - 256;
            ulonglong2 we2 = *(const ulonglong2*)(w1e + w);
            ulonglong2 wo2 = *(const ulonglong2*)(w1o + w);
            ulonglong2 bc2 = *(const ulonglong2*)(b1s + w);
            #pragma unroll
            for (int k4 = 0; k4 < 64; k4 += 4) {
                float4 av0 = *(const float4*)(sa0 + k4);
                float4 av1 = *(const float4*)(sa1 + k4);
                float4 av2 = *(const float4*)(sa2 + k4);
                float4 av3 = *(const float4*)(sa3 + k4);
                float a0r[4] = {av0.x, av0.y, av0.z, av0.w};
                float a1r[4] = {av1.x, av1.y, av1.z, av1.w};
                float a2r[4] = {av2.x, av2.y, av2.z, av2.w};
                float a3r[4] = {av3.x, av3.y, av3.z, av3.w};
                #pragma unroll
                for (int kk = 0; kk < 4; kk++) {
                    int k = k4 + kk;
                    u64 xs = splat2(rxy[2*k]), ys = splat2(rxy[2*k+1]);
                    u64 bv01 = fma2(xs, we2.x, fma2(ys, wo2.x, bc2.x));
                    u64 bv23 = fma2(xs, we2.y, fma2(ys, wo2.y, bc2.y));
                    u64 s0 = splat2(a0r[kk]), s1 = splat2(a1r[kk]);
                    u64 s2 = splat2(a2r[kk]), s3 = splat2(a3r[kk]);
                    acc2[0][0]=fma2(s0,bv01,acc2[0][0]); acc2[0][1]=fma2(s0,bv23,acc2[0][1]);
                    acc2[1][0]=fma2(s1,bv01,acc2[1][0]); acc2[1][1]=fma2(s1,bv23,acc2[1][1]);
                    acc2[2][0]=fma2(s2,bv01,acc2[2][0]); acc2[2][1]=fma2(s2,bv23,acc2[2][1]);
                    acc2[3][0]=fma2(s3,bv01,acc2[3][0]); acc2[3][1]=fma2(s3,bv23,acc2[3][1]);
                }
            }
        }
        float* ctxb = g_ctx + (long)b * 4096;
        #pragma unroll
        for (int hi = 0; hi < 4; hi++) {
            float2 u0 = unpack2(acc2[hi][0]);
            float2 u1 = unpack2(acc2[hi][1]);
            *(float4*)(ctxb + (h0+hi)*512 + j0) = make_float4(u0.x, u0.y, u1.x, u1.y);
        }
    }
}

// ---------------- host launcher ----------------
extern "C" void kernel_launch(void* const* d_in, const int* in_sizes, int n_in,
                              void* d_out, int out_size) {
    const float* Z          = (const float*)d_in[0];
    const float* Q          = (const float*)d_in[1];
    const float* q_z        = (const float*)d_in[2];
    const float* r          = (const float*)d_in[3];
    const float* w1         = (const float*)d_in[4];
    const float* b1         = (const float*)d_in[5];
    const float* w2         = (const float*)d_in[6];
    const float* b2         = (const float*)d_in[7];
    const float* in_proj_w  = (const float*)d_in[8];
    const float* in_proj_b  = (const float*)d_in[9];
    const float* out_proj_w = (const float*)d_in[10];
    const float* out_proj_b = (const float*)d_in[11];
    float* outp = (float*)d_out;

    int* pFlags;
    cudaGetSymbolAddress((void**)&pFlags, g_flags);
    cudaMemsetAsync(pFlags, 0, 32 * sizeof(int));

    cudaFuncSetAttribute(attn_kernel,
                         cudaFuncAttributeMaxDynamicSharedMemorySize, ATTN_SMEM);

    // 1) transpose Z -> Zt
    transpose_kernel<<<dim3((HWn*HWn)/32, Cn/32), dim3(32, 8)>>>(Z);

    // 2) fat: gemm1(fused query) + qz->out copy + interp
    fat_kernel<<<FAT_INTERP_OFF + NPn/32, 256>>>(
        r, q_z, Q, w2, b2, in_proj_w, in_proj_b, outp);

    // 3) qk
    qk_kernel<<<dim3(En/64, SQn/128, NHn), 256>>>(in_proj_w);

    // 4) attention
    attn_kernel<<<SQn, 256, ATTN_SMEM>>>(r, w1, b1);

    // 5) v-gemm + out-gemm fused (flag-pipelined, homogeneous footprint)
    vout_kernel<<<256, 256>>>(in_proj_w, in_proj_b, out_proj_w, out_proj_b, outp);
}

// round 14
// speedup vs baseline: 1.1440x; 1.0517x over previous
#include <cuda_runtime.h>
#include <math.h>
#include <stdint.h>

#define SQn   2048
#define SKn   64
#define Cn    256
#define HWn   256
#define En    512
#define NPn   (SQn*SKn)
#define NHn   8
#define HDn   64

typedef unsigned long long u64;

__device__ __forceinline__ u64 fma2(u64 a, u64 b, u64 c) {
    u64 d;
    asm("fma.rn.f32x2 %0, %1, %2, %3;" : "=l"(d) : "l"(a), "l"(b), "l"(c));
    return d;
}
__device__ __forceinline__ u64 pack2(float lo, float hi) {
    u64 v;
    asm("mov.b64 %0, {%1, %2};" : "=l"(v) : "f"(lo), "f"(hi));
    return v;
}
__device__ __forceinline__ float2 unpack2(u64 v) {
    float lo, hi;
    asm("mov.b64 {%0, %1}, %2;" : "=f"(lo), "=f"(hi) : "l"(v));
    return make_float2(lo, hi);
}
__device__ __forceinline__ u64 splat2(float a) { return pack2(a, a); }

// ---------------- scratch ----------------
__device__ float g_Zt[(size_t)Cn*HWn*HWn];
__device__ float g_key2[(size_t)NPn*256];
__device__ float g_ql[(size_t)SQn*En];
__device__ float g_qk[(size_t)SQn*NHn*En];
__device__ float g_ctx[(size_t)SQn*NHn*En];
__device__ float g_out1[(size_t)SQn*En];
__device__ int   g_flags[16];    // gemm1 m-tile counts (target 8 each)

__device__ __forceinline__ int ld_acq(const int* p) {
    int v;
    asm volatile("ld.acquire.gpu.global.b32 %0, [%1];" : "=r"(v) : "l"(p) : "memory");
    return v;
}
__device__ __forceinline__ void flag_release(int idx, int t) {
    __syncthreads();
    __threadfence();
    if (t == 0) atomicAdd(&g_flags[idx], 1);
}
__device__ __forceinline__ void flag_acquire(int idx, int target, int t) {
    if (t == 0) {
        while (ld_acq(&g_flags[idx]) < target) __nanosleep(256);
    }
    __syncthreads();
}

// ---------------- 1) transpose Z (C, HW*HW) -> Zt (HW*HW, C) ----------------
__global__ void transpose_kernel(const float* __restrict__ Z) {
    __shared__ float tile[32][33];
    int xy0 = blockIdx.x * 32;
    int c0  = blockIdx.y * 32;
    int tx = threadIdx.x, ty = threadIdx.y;   // 32 x 8
    #pragma unroll
    for (int i = 0; i < 32; i += 8)
        tile[ty + i][tx] = Z[(long)(c0 + ty + i) * (HWn*HWn) + xy0 + tx];
    __syncthreads();
    #pragma unroll
    for (int i = 0; i < 32; i += 8)
        g_Zt[(long)(xy0 + ty + i) * Cn + c0 + tx] = tile[tx][ty + i];
}

// ============ proven 128x64 f32x2 GEMM body ============
// C[m][n] = sum_k A[m*lda+k] * B[n*ldbn + k*ldbk] + bias[n]
__device__ __forceinline__ void gemm128_body(
    float* As, float* Bs, int t,
    const float* __restrict__ A, int lda,
    const float* __restrict__ B, int ldbn, int ldbk,
    float* __restrict__ Cp, int ldc, const float* __restrict__ bias,
    int m0, int n0, int K)
{
    int tx = t & 15, ty = t >> 4;
    int ar = t >> 2, ac = (t & 3) * 4;
    const bool bvec = (ldbk == 1);
    const float* Abase = A + (long)(m0 + ar) * lda + ac;

    float4 ra0 = *(const float4*)(Abase);
    float4 ra1 = *(const float4*)(Abase + (long)64 * lda);
    float4 rb; float rbs[4];
    if (bvec) {
        rb = *(const float4*)(B + (long)(n0 + ar) * ldbn + ac);
    } else {
        #pragma unroll
        for (int q = 0; q < 4; q++) {
            int idx = t + 256*q; int nn = idx & 63, kk = idx >> 6;
            rbs[q] = B[(long)(n0 + nn) + (long)kk * ldbk];
        }
    }

    u64 acc2[4][4] = {};
    for (int k0 = 0; k0 < K; k0 += 16) {
        As[(ac+0)*132+ar]=ra0.x; As[(ac+1)*132+ar]=ra0.y; As[(ac+2)*132+ar]=ra0.z; As[(ac+3)*132+ar]=ra0.w;
        As[(ac+0)*132+ar+64]=ra1.x; As[(ac+1)*132+ar+64]=ra1.y; As[(ac+2)*132+ar+64]=ra1.z; As[(ac+3)*132+ar+64]=ra1.w;
        if (bvec) {
            Bs[(ac+0)*68+ar]=rb.x; Bs[(ac+1)*68+ar]=rb.y; Bs[(ac+2)*68+ar]=rb.z; Bs[(ac+3)*68+ar]=rb.w;
        } else {
            #pragma unroll
            for (int q = 0; q < 4; q++) {
                int idx = t + 256*q; int nn = idx & 63, kk = idx >> 6;
                Bs[kk*68+nn] = rbs[q];
            }
        }
        __syncthreads();
        if (k0 + 16 < K) {
            const float* An = Abase + k0 + 16;
            ra0 = *(const float4*)(An);
            ra1 = *(const float4*)(An + (long)64 * lda);
            if (bvec) {
                rb = *(const float4*)(B + (long)(n0 + ar) * ldbn + k0 + 16 + ac);
            } else {
                #pragma unroll
                for (int q = 0; q < 4; q++) {
                    int idx = t + 256*q; int nn = idx & 63, kk = idx >> 6;
                    rbs[q] = B[(long)(n0 + nn) + (long)(k0 + 16 + kk) * ldbk];
                }
            }
        }
        #pragma unroll
        for (int k = 0; k < 16; k++) {
            ulonglong2 aA = *(const ulonglong2*)(&As[k*132 + ty*8]);
            ulonglong2 aB = *(const ulonglong2*)(&As[k*132 + ty*8 + 4]);
            float4 bq = *(const float4*)(&Bs[k*68 + tx*4]);
            u64 bs0=splat2(bq.x), bs1=splat2(bq.y), bs2=splat2(bq.z), bs3=splat2(bq.w);
            acc2[0][0]=fma2(aA.x,bs0,acc2[0][0]); acc2[0][1]=fma2(aA.x,bs1,acc2[0][1]);
            acc2[0][2]=fma2(aA.x,bs2,acc2[0][2]); acc2[0][3]=fma2(aA.x,bs3,acc2[0][3]);
            acc2[1][0]=fma2(aA.y,bs0,acc2[1][0]); acc2[1][1]=fma2(aA.y,bs1,acc2[1][1]);
            acc2[1][2]=fma2(aA.y,bs2,acc2[1][2]); acc2[1][3]=fma2(aA.y,bs3,acc2[1][3]);
            acc2[2][0]=fma2(aB.x,bs0,acc2[2][0]); acc2[2][1]=fma2(aB.x,bs1,acc2[2][1]);
            acc2[2][2]=fma2(aB.x,bs2,acc2[2][2]); acc2[2][3]=fma2(aB.x,bs3,acc2[2][3]);
            acc2[3][0]=fma2(aB.y,bs0,acc2[3][0]); acc2[3][1]=fma2(aB.y,bs1,acc2[3][1]);
            acc2[3][2]=fma2(aB.y,bs2,acc2[3][2]); acc2[3][3]=fma2(aB.y,bs3,acc2[3][3]);
        }
        __syncthreads();
    }
    float4 bb = make_float4(0.f,0.f,0.f,0.f);
    if (bias) bb = *(const float4*)(bias + n0 + tx*4);
    #pragma unroll
    for (int mp = 0; mp < 4; mp++) {
        float2 u0=unpack2(acc2[mp][0]), u1=unpack2(acc2[mp][1]);
        float2 u2=unpack2(acc2[mp][2]), u3=unpack2(acc2[mp][3]);
        int mA = m0 + ty*8 + mp*2, mB = mA + 1;
        *(float4*)(&Cp[(long)mA*ldc + n0 + tx*4]) =
            make_float4(u0.x+bb.x, u1.x+bb.y, u2.x+bb.z, u3.x+bb.w);
        *(float4*)(&Cp[(long)mB*ldc + n0 + tx*4]) =
            make_float4(u0.y+bb.x, u1.y+bb.y, u2.y+bb.z, u3.y+bb.w);
    }
}

// ---------------- 2) FAT kernel: gemm1 | qz->out copy | interp | qk(flags, tail) ----------------
#define FAT_GEMM_BLKS 128
#define FAT_COPY_OFF  FAT_GEMM_BLKS
#define FAT_INTERP_OFF (FAT_COPY_OFF + 16)
#define FAT_QK_OFF    (FAT_INTERP_OFF + 4096)
#define FAT_END       (FAT_QK_OFF + 1024)

struct InterpS { float sres[256][33]; int soff[32]; float sdx[32], sdy[32]; };
struct GemmS   { float As[16][132]; float Bs[16][68]; };

__global__ __launch_bounds__(256)
void fat_kernel(const float* __restrict__ r,
                const float* __restrict__ q_z,
                const float* __restrict__ Q,
                const float* __restrict__ w2,
                const float* __restrict__ b2,
                const float* __restrict__ in_proj_w,
                const float* __restrict__ in_proj_b,
                float* __restrict__ outp) {
    __shared__ __align__(16) char smraw[sizeof(InterpS)];
    int bx = blockIdx.x;
    int t = threadIdx.x;

    if (bx < FAT_GEMM_BLKS) {
        // ---- gemm1 (fused query A) -> g_ql; release m-tile flag ----
        GemmS* S = (GemmS*)smraw;
        int tx = t & 15, ty = t >> 4;
        int m0 = (bx >> 3) * 128;
        int n0 = (bx & 7) * 64;
        int ar = t >> 2, ac = (t & 3) * 4;

        int rowA = m0 + ar, rowB = m0 + ar + 64;
        float qa0 = Q[rowA*3+0], qa1 = Q[rowA*3+1], qa2 = Q[rowA*3+2];
        float qb0 = Q[rowB*3+0], qb1 = Q[rowB*3+1], qb2 = Q[rowB*3+2];

        auto loadA = [&](int row, float q0, float q1, float q2, int k)->float4 {
            if (k < 256) {
                return *(const float4*)(q_z + (long)row*256 + k);
            } else {
                int h = k - 256;
                const float* w2r = w2 + h*3;
                float4 v;
                v.x = q0*w2r[0] + q1*w2r[1]  + q2*w2r[2]  + b2[h+0];
                v.y = q0*w2r[3] + q1*w2r[4]  + q2*w2r[5]  + b2[h+1];
                v.z = q0*w2r[6] + q1*w2r[7]  + q2*w2r[8]  + b2[h+2];
                v.w = q0*w2r[9] + q1*w2r[10] + q2*w2r[11] + b2[h+3];
                return v;
            }
        };

        float4 ra0 = loadA(rowA, qa0, qa1, qa2, ac);
        float4 ra1 = loadA(rowB, qb0, qb1, qb2, ac);
        float4 rb  = *(const float4*)(in_proj_w + (long)(n0 + ar) * En + ac);

        u64 acc2[4][4] = {};
        for (int k0 = 0; k0 < En; k0 += 16) {
            S->As[ac+0][ar]    = ra0.x; S->As[ac+1][ar]    = ra0.y; S->As[ac+2][ar]    = ra0.z; S->As[ac+3][ar]    = ra0.w;
            S->As[ac+0][ar+64] = ra1.x; S->As[ac+1][ar+64] = ra1.y; S->As[ac+2][ar+64] = ra1.z; S->As[ac+3][ar+64] = ra1.w;
            S->Bs[ac+0][ar] = rb.x; S->Bs[ac+1][ar] = rb.y; S->Bs[ac+2][ar] = rb.z; S->Bs[ac+3][ar] = rb.w;
            __syncthreads();
            if (k0 + 16 < En) {
                ra0 = loadA(rowA, qa0, qa1, qa2, k0 + 16 + ac);
                ra1 = loadA(rowB, qb0, qb1, qb2, k0 + 16 + ac);
                rb  = *(const float4*)(in_proj_w + (long)(n0 + ar) * En + k0 + 16 + ac);
            }
            #pragma unroll
            for (int k = 0; k < 16; k++) {
                ulonglong2 aA = *(const ulonglong2*)(&S->As[k][ty*8]);
                ulonglong2 aB = *(const ulonglong2*)(&S->As[k][ty*8+4]);
                float4 bq = *(const float4*)(&S->Bs[k][tx*4]);
                u64 ap0 = aA.x, ap1 = aA.y, ap2 = aB.x, ap3 = aB.y;
                u64 bs0 = splat2(bq.x), bs1 = splat2(bq.y), bs2 = splat2(bq.z), bs3 = splat2(bq.w);
                acc2[0][0]=fma2(ap0,bs0,acc2[0][0]); acc2[0][1]=fma2(ap0,bs1,acc2[0][1]);
                acc2[0][2]=fma2(ap0,bs2,acc2[0][2]); acc2[0][3]=fma2(ap0,bs3,acc2[0][3]);
                acc2[1][0]=fma2(ap1,bs0,acc2[1][0]); acc2[1][1]=fma2(ap1,bs1,acc2[1][1]);
                acc2[1][2]=fma2(ap1,bs2,acc2[1][2]); acc2[1][3]=fma2(ap1,bs3,acc2[1][3]);
                acc2[2][0]=fma2(ap2,bs0,acc2[2][0]); acc2[2][1]=fma2(ap2,bs1,acc2[2][1]);
                acc2[2][2]=fma2(ap2,bs2,acc2[2][2]); acc2[2][3]=fma2(ap2,bs3,acc2[2][3]);
                acc2[3][0]=fma2(ap3,bs0,acc2[3][0]); acc2[3][1]=fma2(ap3,bs1,acc2[3][1]);
                acc2[3][2]=fma2(ap3,bs2,acc2[3][2]); acc2[3][3]=fma2(ap3,bs3,acc2[3][3]);
            }
            __syncthreads();
        }
        float4 bb = *(const float4*)(in_proj_b + n0 + tx*4);
        #pragma unroll
        for (int mp = 0; mp < 4; mp++) {
            float2 u0 = unpack2(acc2[mp][0]);
            float2 u1 = unpack2(acc2[mp][1]);
            float2 u2 = unpack2(acc2[mp][2]);
            float2 u3 = unpack2(acc2[mp][3]);
            int mA = m0 + ty*8 + mp*2, mB = mA + 1;
            *(float4*)(&g_ql[(long)mA * En + n0 + tx*4]) =
                make_float4(u0.x+bb.x, u1.x+bb.y, u2.x+bb.z, u3.x+bb.w);
            *(float4*)(&g_ql[(long)mB * En + n0 + tx*4]) =
                make_float4(u0.y+bb.x, u1.y+bb.y, u2.y+bb.z, u3.y+bb.w);
        }
        flag_release(bx >> 3, t);
    } else if (bx < FAT_INTERP_OFF) {
        // ---- q_z -> outp[:, 0:256) ----
        int r0 = (bx - FAT_COPY_OFF) * 128;
        #pragma unroll
        for (int i = 0; i < 32; i++) {
            int idx = i * 256 + t;
            int row = r0 + (idx >> 6);
            int c4  = (idx & 63) * 4;
            float4 v = *(const float4*)(q_z + (long)row*256 + c4);
            *(float4*)(outp + (long)row*768 + c4) = v;
        }
    } else if (bx < FAT_QK_OFF) {
        // ---- bilinear interp ----
        InterpS* S = (InterpS*)smraw;
        int p0 = (bx - FAT_INTERP_OFF) * 32;
        if (t < 32) {
            float x = r[2*(p0+t)], y = r[2*(p0+t)+1];
            int x1 = (int)x, y1 = (int)y;
            S->soff[t] = (x1*HWn + y1)*Cn;
            S->sdx[t] = x - (float)x1;
            S->sdy[t] = y - (float)y1;
        }
        __syncthreads();
        int wp = t >> 5, l = t & 31;
        #pragma unroll
        for (int pi = 0; pi < 4; pi++) {
            int pl = wp*4 + pi;
            long off = S->soff[pl];
            float dx = S->sdx[pl], dy = S->sdy[pl];
            float omdx = 1.0f - dx, omdy = 1.0f - dy;
            #pragma unroll
            for (int rep = 0; rep < 2; rep++) {
                int c = rep*128 + l*4;
                const float* z11 = g_Zt + off + c;
                float4 a  = *(const float4*)(z11);
                float4 cq = *(const float4*)(z11 + Cn);
                float4 b  = *(const float4*)(z11 + HWn*Cn);
                float4 d  = *(const float4*)(z11 + HWn*Cn + Cn);
                S->sres[c+0][pl] = (a.x*omdx + b.x*dx)*omdy + (cq.x*omdx + d.x*dx)*dy;
                S->sres[c+1][pl] = (a.y*omdx + b.y*dx)*omdy + (cq.y*omdx + d.y*dx)*dy;
                S->sres[c+2][pl] = (a.z*omdx + b.z*dx)*omdy + (cq.z*omdx + d.z*dx)*dy;
                S->sres[c+3][pl] = (a.w*omdx + b.w*dx)*omdy + (cq.w*omdx + d.w*dx)*dy;
            }
        }
        __syncthreads();
        long rowhi = (long)(p0 >> 8);
        int  colb  = p0 & 255;
        #pragma unroll
        for (int i = 0; i < 32; i++) {
            int c = wp*32 + i;
            g_key2[((long)c*512 + rowhi)*256 + colb + l] = S->sres[c][l];
        }
    } else {
        // ---- qk gemm tail: scheduled last, waits on gemm1 m-tile flags ----
        int qi = bx - FAT_QK_OFF;
        int ni = qi & 7, mi = (qi >> 3) & 15, h = qi >> 7;
        flag_acquire(mi, 8, t);
        float* As = (float*)smraw;
        gemm128_body(As, As + 16*132, t,
                     g_ql + (long)h*HDn, En,
                     in_proj_w + (long)En*En + (long)h*HDn*En, 1, En,
                     g_qk + (long)h*En, NHn*En, (const float*)0,
                     mi*128, ni*64, HDn);
    }
}

// ---------------- generic GEMM kernel (128x64, batched) for v / out ----------------
__global__ __launch_bounds__(256)
void gemm_kernel(const float* __restrict__ A, int lda, long sA,
                 const float* __restrict__ B, int ldbn, int ldbk, long sB,
                 float* __restrict__ Cp, int ldc, long sC,
                 const float* __restrict__ bias, long sBias, int K) {
    __shared__ float sm[16*132 + 16*68];
    int b = blockIdx.z;
    gemm128_body(sm, sm + 16*132, threadIdx.x,
                 A + (long)b*sA, lda,
                 B + (long)b*sB, ldbn, ldbk,
                 Cp + (long)b*sC, ldc,
                 bias ? bias + (long)b*sBias : (const float*)0,
                 blockIdx.y*128, blockIdx.x*64, K);
}

// ---------------- 4) fused attention (R8, unchanged) ----------------
#define SKS 268
#define SQS 516
#define OFF_SQ   17152
#define OFF_RED  21280
#define OFF_SC   25376
#define OFF_SA   25888
#define OFF_SMAX 26400
#define OFF_SRS  26408
#define OFF_RXY  26416
#define OFF_W1E  26544
#define OFF_W1O  26800
#define OFF_B1S  27056
#define ATTN_FLTS 27312
#define ATTN_SMEM (ATTN_FLTS*4)

__global__ __launch_bounds__(256, 2)
void attn_kernel(const float* __restrict__ r, const float* __restrict__ w1,
                 const float* __restrict__ b1) {
    extern __shared__ float smf[];
    float* skey = smf;
    float* sq   = smf + OFF_SQ;
    float* red  = smf + OFF_RED;
    float* sc   = smf + OFF_SC;
    float* sa   = smf + OFF_SA;
    float* smax = smf + OFF_SMAX;
    float* srs  = smf + OFF_SRS;
    float* rxy  = smf + OFF_RXY;
    float* w1e  = smf + OFF_W1E;
    float* w1o  = smf + OFF_W1O;
    float* b1s  = smf + OFF_B1S;

    int b = blockIdx.x, t = threadIdx.x;

    const float* keyb = g_key2 + (long)b * (64*256);
    #pragma unroll
    for (int q = 0; q < 16; q++) {
        int idx = t + 256*q;
        int row = idx >> 6, c4 = (idx & 63) * 4;
        *(float4*)(skey + row*SKS + c4) = *(const float4*)(keyb + row*256 + c4);
    }
    {
        const float4* qsrc = (const float4*)(g_qk + (long)b * 4096);
        #pragma unroll
        for (int q = 0; q < 4; q++) {
            int idx = t + 256*q;
            int row = idx >> 7, c = idx & 127;
            *(float4*)(sq + row*SQS + c*4) = qsrc[row*128 + c];
        }
    }
    if (t < 128) rxy[t] = r[b*128 + t];
    w1e[t] = w1[2*t]; w1o[t] = w1[2*t+1]; b1s[t] = b1[t];
    __syncthreads();

    {
        int s = t >> 5, lane = t & 31;
        int hq = lane >> 4, kq = lane & 15;
        int h0 = hq * 4, jb = s * 32;
        u64 acc2[4][4] = {};
        #pragma unroll
        for (int st = 0; st < 8; st++) {
            int jj = jb + st*4;
            ulonglong2 a0 = *(const ulonglong2*)(sq + (h0+0)*SQS + jj);
            ulonglong2 a1 = *(const ulonglong2*)(sq + (h0+1)*SQS + jj);
            ulonglong2 a2 = *(const ulonglong2*)(sq + (h0+2)*SQS + jj);
            ulonglong2 a3 = *(const ulonglong2*)(sq + (h0+3)*SQS + jj);
            #pragma unroll
            for (int m = 0; m < 4; m++) {
                ulonglong2 bv = *(const ulonglong2*)(skey + (kq + 16*m)*SKS + jj);
                acc2[0][m] = fma2(a0.x, bv.x, acc2[0][m]); acc2[0][m] = fma2(a0.y, bv.y, acc2[0][m]);
                acc2[1][m] = fma2(a1.x, bv.x, acc2[1][m]); acc2[1][m] = fma2(a1.y, bv.y, acc2[1][m]);
                acc2[2][m] = fma2(a2.x, bv.x, acc2[2][m]); acc2[2][m] = fma2(a2.y, bv.y, acc2[2][m]);
                acc2[3][m] = fma2(a3.x, bv.x, acc2[3][m]); acc2[3][m] = fma2(a3.y, bv.y, acc2[3][m]);
            }
        }
        u64 xs[4], ys[4];
        #pragma unroll
        for (int m = 0; m < 4; m++) {
            int k = kq + 16*m;
            xs[m] = splat2(rxy[2*k]);
            ys[m] = splat2(rxy[2*k+1]);
        }
        #pragma unroll
        for (int st = 0; st < 8; st++) {
            int w = jb + st*4, jj = 256 + w;
            ulonglong2 a0 = *(const ulonglong2*)(sq + (h0+0)*SQS + jj);
            ulonglong2 a1 = *(const ulonglong2*)(sq + (h0+1)*SQS + jj);
            ulonglong2 a2 = *(const ulonglong2*)(sq + (h0+2)*SQS + jj);
            ulonglong2 a3 = *(const ulonglong2*)(sq + (h0+3)*SQS + jj);
            ulonglong2 we2 = *(const ulonglong2*)(w1e + w);
            ulonglong2 wo2 = *(const ulonglong2*)(w1o + w);
            ulonglong2 bc2 = *(const ulonglong2*)(b1s + w);
            #pragma unroll
            for (int m = 0; m < 4; m++) {
                u64 bv01 = fma2(xs[m], we2.x, fma2(ys[m], wo2.x, bc2.x));
                u64 bv23 = fma2(xs[m], we2.y, fma2(ys[m], wo2.y, bc2.y));
                acc2[0][m] = fma2(a0.x, bv01, acc2[0][m]); acc2[0][m] = fma2(a0.y, bv23, acc2[0][m]);
                acc2[1][m] = fma2(a1.x, bv01, acc2[1][m]); acc2[1][m] = fma2(a1.y, bv23, acc2[1][m]);
                acc2[2][m] = fma2(a2.x, bv01, acc2[2][m]); acc2[2][m] = fma2(a2.y, bv23, acc2[2][m]);
                acc2[3][m] = fma2(a3.x, bv01, acc2[3][m]); acc2[3][m] = fma2(a3.y, bv23, acc2[3][m]);
            }
        }
        #pragma unroll
        for (int hi = 0; hi < 4; hi++)
            #pragma unroll
            for (int m = 0; m < 4; m++) {
                float2 u = unpack2(acc2[hi][m]);
                red[s*512 + (h0+hi)*64 + m*16 + kq] = u.x + u.y;
            }
    }
    __syncthreads();
    #pragma unroll
    for (int e0 = 0; e0 < 2; e0++) {
        int e = t + e0*256;
        float v = 0.f;
        #pragma unroll
        for (int s2 = 0; s2 < 8; s2++) v += red[s2*512 + e];
        sc[e] = v * 0.125f;
    }
    __syncthreads();

    if (t < 32) {
        int h = t >> 2, seg = t & 3;
        const float* p = sc + h*64 + seg*16;
        float mx = p[0];
        #pragma unroll
        for (int i = 1; i < 16; i++) mx = fmaxf(mx, p[i]);
        mx = fmaxf(mx, __shfl_xor_sync(0xffffffffu, mx, 1));
        mx = fmaxf(mx, __shfl_xor_sync(0xffffffffu, mx, 2));
        float sm = 0.f;
        #pragma unroll
        for (int i = 0; i < 16; i++) sm += __expf(p[i] - mx);
        sm += __shfl_xor_sync(0xffffffffu, sm, 1);
        sm += __shfl_xor_sync(0xffffffffu, sm, 2);
        if (seg == 0) { smax[h] = mx; srs[h] = 1.0f / sm; }
    }
    __syncthreads();
    sa[t]     = __expf(sc[t]     - smax[t >> 6])       * srs[t >> 6];
    sa[t+256] = __expf(sc[t+256] - smax[(t+256) >> 6]) * srs[(t+256) >> 6];
    __syncthreads();

    {
        int hq = t >> 7, jq = t & 127;
        int h0 = hq * 4, j0 = jq * 4;
        const float* sa0 = sa + (h0+0)*64;
        const float* sa1 = sa + (h0+1)*64;
        const float* sa2 = sa + (h0+2)*64;
        const float* sa3 = sa + (h0+3)*64;
        u64 acc2[4][2] = {};
        if (j0 < 256) {
            #pragma unroll
            for (int k4 = 0; k4 < 64; k4 += 4) {
                float4 av0 = *(const float4*)(sa0 + k4);
                float4 av1 = *(const float4*)(sa1 + k4);
                float4 av2 = *(const float4*)(sa2 + k4);
                float4 av3 = *(const float4*)(sa3 + k4);
                float a0r[4] = {av0.x, av0.y, av0.z, av0.w};
                float a1r[4] = {av1.x, av1.y, av1.z, av1.w};
                float a2r[4] = {av2.x, av2.y, av2.z, av2.w};
                float a3r[4] = {av3.x, av3.y, av3.z, av3.w};
                #pragma unroll
                for (int kk = 0; kk < 4; kk++) {
                    ulonglong2 bv = *(const ulonglong2*)(skey + (k4+kk)*SKS + j0);
                    u64 s0 = splat2(a0r[kk]), s1 = splat2(a1r[kk]);
                    u64 s2 = splat2(a2r[kk]), s3 = splat2(a3r[kk]);
                    acc2[0][0]=fma2(s0,bv.x,acc2[0][0]); acc2[0][1]=fma2(s0,bv.y,acc2[0][1]);
                    acc2[1][0]=fma2(s1,bv.x,acc2[1][0]); acc2[1][1]=fma2(s1,bv.y,acc2[1][1]);
                    acc2[2][0]=fma2(s2,bv.x,acc2[2][0]); acc2[2][1]=fma2(s2,bv.y,acc2[2][1]);
                    acc2[3][0]=fma2(s3,bv.x,acc2[3][0]); acc2[3][1]=fma2(s3,bv.y,acc2[3][1]);
                }
            }
        } else {
            int w = j0 - 256;
            ulonglong2 we2 = *(const ulonglong2*)(w1e + w);
            ulonglong2 wo2 = *(const ulonglong2*)(w1o + w);
            ulonglong2 bc2 = *(const ulonglong2*)(b1s + w);
            #pragma unroll
            for (int k4 = 0; k4 < 64; k4 += 4) {
                float4 av0 = *(const float4*)(sa0 + k4);
                float4 av1 = *(const float4*)(sa1 + k4);
                float4 av2 = *(const float4*)(sa2 + k4);
                float4 av3 = *(const float4*)(sa3 + k4);
                float a0r[4] = {av0.x, av0.y, av0.z, av0.w};
                float a1r[4] = {av1.x, av1.y, av1.z, av1.w};
                float a2r[4] = {av2.x, av2.y, av2.z, av2.w};
                float a3r[4] = {av3.x, av3.y, av3.z, av3.w};
                #pragma unroll
                for (int kk = 0; kk < 4; kk++) {
                    int k = k4 + kk;
                    u64 xs = splat2(rxy[2*k]), ys = splat2(rxy[2*k+1]);
                    u64 bv01 = fma2(xs, we2.x, fma2(ys, wo2.x, bc2.x));
                    u64 bv23 = fma2(xs, we2.y, fma2(ys, wo2.y, bc2.y));
                    u64 s0 = splat2(a0r[kk]), s1 = splat2(a1r[kk]);
                    u64 s2 = splat2(a2r[kk]), s3 = splat2(a3r[kk]);
                    acc2[0][0]=fma2(s0,bv01,acc2[0][0]); acc2[0][1]=fma2(s0,bv23,acc2[0][1]);
                    acc2[1][0]=fma2(s1,bv01,acc2[1][0]); acc2[1][1]=fma2(s1,bv23,acc2[1][1]);
                    acc2[2][0]=fma2(s2,bv01,acc2[2][0]); acc2[2][1]=fma2(s2,bv23,acc2[2][1]);
                    acc2[3][0]=fma2(s3,bv01,acc2[3][0]); acc2[3][1]=fma2(s3,bv23,acc2[3][1]);
                }
            }
        }
        float* ctxb = g_ctx + (long)b * 4096;
        #pragma unroll
        for (int hi = 0; hi < 4; hi++) {
            float2 u0 = unpack2(acc2[hi][0]);
            float2 u1 = unpack2(acc2[hi][1]);
            *(float4*)(ctxb + (h0+hi)*512 + j0) = make_float4(u0.x, u0.y, u1.x, u1.y);
        }
    }
}

// ---------------- host launcher ----------------
extern "C" void kernel_launch(void* const* d_in, const int* in_sizes, int n_in,
                              void* d_out, int out_size) {
    const float* Z          = (const float*)d_in[0];
    const float* Q          = (const float*)d_in[1];
    const float* q_z        = (const float*)d_in[2];
    const float* r          = (const float*)d_in[3];
    const float* w1         = (const float*)d_in[4];
    const float* b1         = (const float*)d_in[5];
    const float* w2         = (const float*)d_in[6];
    const float* b2         = (const float*)d_in[7];
    const float* in_proj_w  = (const float*)d_in[8];
    const float* in_proj_b  = (const float*)d_in[9];
    const float* out_proj_w = (const float*)d_in[10];
    const float* out_proj_b = (const float*)d_in[11];
    float* outp = (float*)d_out;

    float *pCtx, *pOut1;
    int* pFlags;
    cudaGetSymbolAddress((void**)&pCtx,   g_ctx);
    cudaGetSymbolAddress((void**)&pOut1,  g_out1);
    cudaGetSymbolAddress((void**)&pFlags, g_flags);

    cudaMemsetAsync(pFlags, 0, 16 * sizeof(int));

    cudaFuncSetAttribute(attn_kernel,
                         cudaFuncAttributeMaxDynamicSharedMemorySize, ATTN_SMEM);

    // 1) transpose Z -> Zt
    transpose_kernel<<<dim3((HWn*HWn)/32, Cn/32), dim3(32, 8)>>>(Z);

    // 2) fat: gemm1 + qz-copy + interp + qk tail (flag-dep on gemm1)
    fat_kernel<<<FAT_END, 256>>>(r, q_z, Q, w2, b2, in_proj_w, in_proj_b, outp);

    // 3) attention
    attn_kernel<<<SQn, 256, ATTN_SMEM>>>(r, w1, b1);

    // 4) v: out1[m][h*64+:] = ctx[m][h][:] . Wv_h + bv
    gemm_kernel<<<dim3(1, SQn/128, NHn), 256>>>(
        pCtx, NHn*En, (long)En,
        in_proj_w + (long)2*En*En, En, 1, (long)HDn*En,
        pOut1, En, (long)HDn,
        in_proj_b + (long)2*En, (long)HDn, En);

    // 5) out_proj into d_out cols [256,768)
    gemm_kernel<<<dim3(En/64, SQn/128, 1), 256>>>(
        pOut1, En, 0L,
        out_proj_w, En, 1, 0L,
        outp + 256, 768, 0L,
        out_proj_b, 0L, En);
}

// round 15
// speedup vs baseline: 1.1479x; 1.0034x over previous
#include <cuda_runtime.h>
#include <math.h>
#include <stdint.h>

#define SQn   2048
#define SKn   64
#define Cn    256
#define HWn   256
#define En    512
#define NPn   (SQn*SKn)
#define NHn   8
#define HDn   64

typedef unsigned long long u64;

__device__ __forceinline__ u64 fma2(u64 a, u64 b, u64 c) {
    u64 d;
    asm("fma.rn.f32x2 %0, %1, %2, %3;" : "=l"(d) : "l"(a), "l"(b), "l"(c));
    return d;
}
__device__ __forceinline__ u64 pack2(float lo, float hi) {
    u64 v;
    asm("mov.b64 %0, {%1, %2};" : "=l"(v) : "f"(lo), "f"(hi));
    return v;
}
__device__ __forceinline__ float2 unpack2(u64 v) {
    float lo, hi;
    asm("mov.b64 {%0, %1}, %2;" : "=f"(lo), "=f"(hi) : "l"(v));
    return make_float2(lo, hi);
}
__device__ __forceinline__ u64 splat2(float a) { return pack2(a, a); }

// ---------------- scratch ----------------
__device__ float g_Zt[(size_t)Cn*HWn*HWn];
__device__ float g_key2[(size_t)NPn*256];
__device__ float g_ql[(size_t)SQn*En];
__device__ float g_qk[(size_t)SQn*NHn*En];
__device__ float g_ctx[(size_t)SQn*NHn*En];
__device__ float g_vp0[(size_t)SQn*En];
__device__ float g_vp1[(size_t)SQn*En];
__device__ float g_op0[(size_t)SQn*En];
__device__ float g_op1[(size_t)SQn*En];

// ---------------- 1) transpose Z (C, HW*HW) -> Zt (HW*HW, C) ----------------
__global__ void transpose_kernel(const float* __restrict__ Z) {
    __shared__ float tile[32][33];
    int xy0 = blockIdx.x * 32;
    int c0  = blockIdx.y * 32;
    int tx = threadIdx.x, ty = threadIdx.y;   // 32 x 8
    #pragma unroll
    for (int i = 0; i < 32; i += 8)
        tile[ty + i][tx] = Z[(long)(c0 + ty + i) * (HWn*HWn) + xy0 + tx];
    __syncthreads();
    #pragma unroll
    for (int i = 0; i < 32; i += 8)
        g_Zt[(long)(xy0 + ty + i) * Cn + c0 + tx] = tile[tx][ty + i];
}

// ============ proven 128x64 f32x2 GEMM body; ASUM mode sums two A buffers + per-k bias ============
// C[m][n] = sum_k Aeff[m][k] * B[n*ldbn + k*ldbk] + bias[n]
// Aeff = A            (ASUM=false)
//      = A + A2 + Akb (ASUM=true; Akb indexed by k)
template<bool ASUM>
__device__ __forceinline__ void gemm128_body(
    float* As, float* Bs, int t,
    const float* __restrict__ A, const float* __restrict__ A2,
    const float* __restrict__ Akb, int lda,
    const float* __restrict__ B, int ldbn, int ldbk,
    float* __restrict__ Cp, int ldc, const float* __restrict__ bias,
    int m0, int n0, int K)
{
    int tx = t & 15, ty = t >> 4;
    int ar = t >> 2, ac = (t & 3) * 4;
    const bool bvec = (ldbk == 1);
    long aoffA = (long)(m0 + ar) * lda;
    long aoffB = (long)(m0 + ar + 64) * lda;

    auto loadA = [&](long off, int k)->float4 {
        float4 v = *(const float4*)(A + off + k);
        if (ASUM) {
            float4 w = *(const float4*)(A2 + off + k);
            float4 bk = *(const float4*)(Akb + k);
            v.x += w.x + bk.x; v.y += w.y + bk.y;
            v.z += w.z + bk.z; v.w += w.w + bk.w;
        }
        return v;
    };

    float4 ra0 = loadA(aoffA, ac);
    float4 ra1 = loadA(aoffB, ac);
    float4 rb; float rbs[4];
    if (bvec) {
        rb = *(const float4*)(B + (long)(n0 + ar) * ldbn + ac);
    } else {
        #pragma unroll
        for (int q = 0; q < 4; q++) {
            int idx = t + 256*q; int nn = idx & 63, kk = idx >> 6;
            rbs[q] = B[(long)(n0 + nn) + (long)kk * ldbk];
        }
    }

    u64 acc2[4][4] = {};
    for (int k0 = 0; k0 < K; k0 += 16) {
        As[(ac+0)*132+ar]=ra0.x; As[(ac+1)*132+ar]=ra0.y; As[(ac+2)*132+ar]=ra0.z; As[(ac+3)*132+ar]=ra0.w;
        As[(ac+0)*132+ar+64]=ra1.x; As[(ac+1)*132+ar+64]=ra1.y; As[(ac+2)*132+ar+64]=ra1.z; As[(ac+3)*132+ar+64]=ra1.w;
        if (bvec) {
            Bs[(ac+0)*68+ar]=rb.x; Bs[(ac+1)*68+ar]=rb.y; Bs[(ac+2)*68+ar]=rb.z; Bs[(ac+3)*68+ar]=rb.w;
        } else {
            #pragma unroll
            for (int q = 0; q < 4; q++) {
                int idx = t + 256*q; int nn = idx & 63, kk = idx >> 6;
                Bs[kk*68+nn] = rbs[q];
            }
        }
        __syncthreads();
        if (k0 + 16 < K) {
            ra0 = loadA(aoffA, k0 + 16 + ac);
            ra1 = loadA(aoffB, k0 + 16 + ac);
            if (bvec) {
                rb = *(const float4*)(B + (long)(n0 + ar) * ldbn + k0 + 16 + ac);
            } else {
                #pragma unroll
                for (int q = 0; q < 4; q++) {
                    int idx = t + 256*q; int nn = idx & 63, kk = idx >> 6;
                    rbs[q] = B[(long)(n0 + nn) + (long)(k0 + 16 + kk) * ldbk];
                }
            }
        }
        #pragma unroll
        for (int k = 0; k < 16; k++) {
            ulonglong2 aA = *(const ulonglong2*)(&As[k*132 + ty*8]);
            ulonglong2 aB = *(const ulonglong2*)(&As[k*132 + ty*8 + 4]);
            float4 bq = *(const float4*)(&Bs[k*68 + tx*4]);
            u64 bs0=splat2(bq.x), bs1=splat2(bq.y), bs2=splat2(bq.z), bs3=splat2(bq.w);
            acc2[0][0]=fma2(aA.x,bs0,acc2[0][0]); acc2[0][1]=fma2(aA.x,bs1,acc2[0][1]);
            acc2[0][2]=fma2(aA.x,bs2,acc2[0][2]); acc2[0][3]=fma2(aA.x,bs3,acc2[0][3]);
            acc2[1][0]=fma2(aA.y,bs0,acc2[1][0]); acc2[1][1]=fma2(aA.y,bs1,acc2[1][1]);
            acc2[1][2]=fma2(aA.y,bs2,acc2[1][2]); acc2[1][3]=fma2(aA.y,bs3,acc2[1][3]);
            acc2[2][0]=fma2(aB.x,bs0,acc2[2][0]); acc2[2][1]=fma2(aB.x,bs1,acc2[2][1]);
            acc2[2][2]=fma2(aB.x,bs2,acc2[2][2]); acc2[2][3]=fma2(aB.x,bs3,acc2[2][3]);
            acc2[3][0]=fma2(aB.y,bs0,acc2[3][0]); acc2[3][1]=fma2(aB.y,bs1,acc2[3][1]);
            acc2[3][2]=fma2(aB.y,bs2,acc2[3][2]); acc2[3][3]=fma2(aB.y,bs3,acc2[3][3]);
        }
        __syncthreads();
    }
    float4 bb = make_float4(0.f,0.f,0.f,0.f);
    if (bias) bb = *(const float4*)(bias + n0 + tx*4);
    #pragma unroll
    for (int mp = 0; mp < 4; mp++) {
        float2 u0=unpack2(acc2[mp][0]), u1=unpack2(acc2[mp][1]);
        float2 u2=unpack2(acc2[mp][2]), u3=unpack2(acc2[mp][3]);
        int mA = m0 + ty*8 + mp*2, mB = mA + 1;
        *(float4*)(&Cp[(long)mA*ldc + n0 + tx*4]) =
            make_float4(u0.x+bb.x, u1.x+bb.y, u2.x+bb.z, u3.x+bb.w);
        *(float4*)(&Cp[(long)mB*ldc + n0 + tx*4]) =
            make_float4(u0.y+bb.x, u1.y+bb.y, u2.y+bb.z, u3.y+bb.w);
    }
}

// ---------------- 2) FAT kernel (R8): gemm1(query fused) | qz->out copy | interp ----------------
#define FAT_GEMM_BLKS 128
#define FAT_COPY_BLKS 16
#define FAT_INTERP_OFF (FAT_GEMM_BLKS + FAT_COPY_BLKS)

struct InterpS { float sres[256][33]; int soff[32]; float sdx[32], sdy[32]; };
struct GemmS   { float As[16][132]; float Bs[16][68]; };

__global__ __launch_bounds__(256)
void fat_kernel(const float* __restrict__ r,
                const float* __restrict__ q_z,
                const float* __restrict__ Q,
                const float* __restrict__ w2,
                const float* __restrict__ b2,
                const float* __restrict__ in_proj_w,
                const float* __restrict__ in_proj_b,
                float* __restrict__ outp) {
    __shared__ __align__(16) char smraw[sizeof(InterpS)];
    int bx = blockIdx.x;
    int t = threadIdx.x;

    if (bx < FAT_GEMM_BLKS) {
        GemmS* S = (GemmS*)smraw;
        int tx = t & 15, ty = t >> 4;
        int m0 = (bx >> 3) * 128;
        int n0 = (bx & 7) * 64;
        int ar = t >> 2, ac = (t & 3) * 4;

        int rowA = m0 + ar, rowB = m0 + ar + 64;
        float qa0 = Q[rowA*3+0], qa1 = Q[rowA*3+1], qa2 = Q[rowA*3+2];
        float qb0 = Q[rowB*3+0], qb1 = Q[rowB*3+1], qb2 = Q[rowB*3+2];

        auto loadA = [&](int row, float q0, float q1, float q2, int k)->float4 {
            if (k < 256) {
                return *(const float4*)(q_z + (long)row*256 + k);
            } else {
                int h = k - 256;
                const float* w2r = w2 + h*3;
                float4 v;
                v.x = q0*w2r[0] + q1*w2r[1]  + q2*w2r[2]  + b2[h+0];
                v.y = q0*w2r[3] + q1*w2r[4]  + q2*w2r[5]  + b2[h+1];
                v.z = q0*w2r[6] + q1*w2r[7]  + q2*w2r[8]  + b2[h+2];
                v.w = q0*w2r[9] + q1*w2r[10] + q2*w2r[11] + b2[h+3];
                return v;
            }
        };

        float4 ra0 = loadA(rowA, qa0, qa1, qa2, ac);
        float4 ra1 = loadA(rowB, qb0, qb1, qb2, ac);
        float4 rb  = *(const float4*)(in_proj_w + (long)(n0 + ar) * En + ac);

        u64 acc2[4][4] = {};
        for (int k0 = 0; k0 < En; k0 += 16) {
            S->As[ac+0][ar]    = ra0.x; S->As[ac+1][ar]    = ra0.y; S->As[ac+2][ar]    = ra0.z; S->As[ac+3][ar]    = ra0.w;
            S->As[ac+0][ar+64] = ra1.x; S->As[ac+1][ar+64] = ra1.y; S->As[ac+2][ar+64] = ra1.z; S->As[ac+3][ar+64] = ra1.w;
            S->Bs[ac+0][ar] = rb.x; S->Bs[ac+1][ar] = rb.y; S->Bs[ac+2][ar] = rb.z; S->Bs[ac+3][ar] = rb.w;
            __syncthreads();
            if (k0 + 16 < En) {
                ra0 = loadA(rowA, qa0, qa1, qa2, k0 + 16 + ac);
                ra1 = loadA(rowB, qb0, qb1, qb2, k0 + 16 + ac);
                rb  = *(const float4*)(in_proj_w + (long)(n0 + ar) * En + k0 + 16 + ac);
            }
            #pragma unroll
            for (int k = 0; k < 16; k++) {
                ulonglong2 aA = *(const ulonglong2*)(&S->As[k][ty*8]);
                ulonglong2 aB = *(const ulonglong2*)(&S->As[k][ty*8+4]);
                float4 bq = *(const float4*)(&S->Bs[k][tx*4]);
                u64 ap0 = aA.x, ap1 = aA.y, ap2 = aB.x, ap3 = aB.y;
                u64 bs0 = splat2(bq.x), bs1 = splat2(bq.y), bs2 = splat2(bq.z), bs3 = splat2(bq.w);
                acc2[0][0]=fma2(ap0,bs0,acc2[0][0]); acc2[0][1]=fma2(ap0,bs1,acc2[0][1]);
                acc2[0][2]=fma2(ap0,bs2,acc2[0][2]); acc2[0][3]=fma2(ap0,bs3,acc2[0][3]);
                acc2[1][0]=fma2(ap1,bs0,acc2[1][0]); acc2[1][1]=fma2(ap1,bs1,acc2[1][1]);
                acc2[1][2]=fma2(ap1,bs2,acc2[1][2]); acc2[1][3]=fma2(ap1,bs3,acc2[1][3]);
                acc2[2][0]=fma2(ap2,bs0,acc2[2][0]); acc2[2][1]=fma2(ap2,bs1,acc2[2][1]);
                acc2[2][2]=fma2(ap2,bs2,acc2[2][2]); acc2[2][3]=fma2(ap2,bs3,acc2[2][3]);
                acc2[3][0]=fma2(ap3,bs0,acc2[3][0]); acc2[3][1]=fma2(ap3,bs1,acc2[3][1]);
                acc2[3][2]=fma2(ap3,bs2,acc2[3][2]); acc2[3][3]=fma2(ap3,bs3,acc2[3][3]);
            }
            __syncthreads();
        }
        float4 bb = *(const float4*)(in_proj_b + n0 + tx*4);
        #pragma unroll
        for (int mp = 0; mp < 4; mp++) {
            float2 u0 = unpack2(acc2[mp][0]);
            float2 u1 = unpack2(acc2[mp][1]);
            float2 u2 = unpack2(acc2[mp][2]);
            float2 u3 = unpack2(acc2[mp][3]);
            int mA = m0 + ty*8 + mp*2, mB = mA + 1;
            *(float4*)(&g_ql[(long)mA * En + n0 + tx*4]) =
                make_float4(u0.x+bb.x, u1.x+bb.y, u2.x+bb.z, u3.x+bb.w);
            *(float4*)(&g_ql[(long)mB * En + n0 + tx*4]) =
                make_float4(u0.y+bb.x, u1.y+bb.y, u2.y+bb.z, u3.y+bb.w);
        }
    } else if (bx < FAT_INTERP_OFF) {
        int r0 = (bx - FAT_GEMM_BLKS) * 128;
        #pragma unroll
        for (int i = 0; i < 32; i++) {
            int idx = i * 256 + t;
            int row = r0 + (idx >> 6);
            int c4  = (idx & 63) * 4;
            float4 v = *(const float4*)(q_z + (long)row*256 + c4);
            *(float4*)(outp + (long)row*768 + c4) = v;
        }
    } else {
        InterpS* S = (InterpS*)smraw;
        int p0 = (bx - FAT_INTERP_OFF) * 32;
        if (t < 32) {
            float x = r[2*(p0+t)], y = r[2*(p0+t)+1];
            int x1 = (int)x, y1 = (int)y;
            S->soff[t] = (x1*HWn + y1)*Cn;
            S->sdx[t] = x - (float)x1;
            S->sdy[t] = y - (float)y1;
        }
        __syncthreads();
        int wp = t >> 5, l = t & 31;
        #pragma unroll
        for (int pi = 0; pi < 4; pi++) {
            int pl = wp*4 + pi;
            long off = S->soff[pl];
            float dx = S->sdx[pl], dy = S->sdy[pl];
            float omdx = 1.0f - dx, omdy = 1.0f - dy;
            #pragma unroll
            for (int rep = 0; rep < 2; rep++) {
                int c = rep*128 + l*4;
                const float* z11 = g_Zt + off + c;
                float4 a  = *(const float4*)(z11);
                float4 cq = *(const float4*)(z11 + Cn);
                float4 b  = *(const float4*)(z11 + HWn*Cn);
                float4 d  = *(const float4*)(z11 + HWn*Cn + Cn);
                S->sres[c+0][pl] = (a.x*omdx + b.x*dx)*omdy + (cq.x*omdx + d.x*dx)*dy;
                S->sres[c+1][pl] = (a.y*omdx + b.y*dx)*omdy + (cq.y*omdx + d.y*dx)*dy;
                S->sres[c+2][pl] = (a.z*omdx + b.z*dx)*omdy + (cq.z*omdx + d.z*dx)*dy;
                S->sres[c+3][pl] = (a.w*omdx + b.w*dx)*omdy + (cq.w*omdx + d.w*dx)*dy;
            }
        }
        __syncthreads();
        long rowhi = (long)(p0 >> 8);
        int  colb  = p0 & 255;
        #pragma unroll
        for (int i = 0; i < 32; i++) {
            int c = wp*32 + i;
            g_key2[((long)c*512 + rowhi)*256 + colb + l] = S->sres[c][l];
        }
    }
}

// ---------------- 3) qk gemm (standalone, proven) ----------------
__global__ __launch_bounds__(256)
void qk_kernel(const float* __restrict__ in_proj_w) {
    __shared__ float sm[16*132 + 16*68];
    int h = blockIdx.z;
    gemm128_body<false>(sm, sm + 16*132, threadIdx.x,
                 g_ql + (long)h*HDn, (const float*)0, (const float*)0, En,
                 in_proj_w + (long)En*En + (long)h*HDn*En, 1, En,
                 g_qk + (long)h*En, NHn*En, (const float*)0,
                 blockIdx.y*128, blockIdx.x*64, HDn);
}

// ---------------- 5) v gemm, K-split by 2 (256 blocks) ----------------
__global__ __launch_bounds__(256)
void vsplit_kernel(const float* __restrict__ in_proj_w) {
    __shared__ float sm[16*132 + 16*68];
    int z = blockIdx.z;
    int h = z & 7, kz = z >> 3;
    float* dst = kz ? g_vp1 : g_vp0;
    gemm128_body<false>(sm, sm + 16*132, threadIdx.x,
                 g_ctx + (long)h*En + kz*256, (const float*)0, (const float*)0, NHn*En,
                 in_proj_w + (long)2*En*En + (long)h*HDn*En + kz*256, En, 1,
                 dst + (long)h*HDn, En, (const float*)0,
                 blockIdx.y*128, 0, 256);
}

// ---------------- 6) out gemm, K-split by 2, A = vp0+vp1+bv on the fly ----------------
__global__ __launch_bounds__(256)
void outsplit_kernel(const float* __restrict__ in_proj_b,
                     const float* __restrict__ out_proj_w) {
    __shared__ float sm[16*132 + 16*68];
    int kz = blockIdx.z;
    float* dst = kz ? g_op1 : g_op0;
    gemm128_body<true>(sm, sm + 16*132, threadIdx.x,
                 g_vp0 + kz*256, g_vp1 + kz*256, in_proj_b + 2*En + kz*256, En,
                 out_proj_w + kz*256, En, 1,
                 dst, En, (const float*)0,
                 blockIdx.y*128, blockIdx.x*64, 256);
}

// ---------------- 7) finalize: outp[:,256:768] = op0 + op1 + bo ----------------
__global__ __launch_bounds__(256)
void finalize_kernel(const float* __restrict__ out_proj_b, float* __restrict__ outp) {
    int idx = blockIdx.x * 512 + threadIdx.x;   // 512 blocks x 256 thr x 2 float4
    #pragma unroll
    for (int rep = 0; rep < 2; rep++) {
        int e = idx + rep * 256;                // float4 index, total 262144
        int row = e >> 7, c4 = (e & 127) * 4;
        float4 a = *(const float4*)(g_op0 + (long)row*512 + c4);
        float4 b = *(const float4*)(g_op1 + (long)row*512 + c4);
        float4 bo = *(const float4*)(out_proj_b + c4);
        float4 o = make_float4(a.x+b.x+bo.x, a.y+b.y+bo.y, a.z+b.z+bo.z, a.w+b.w+bo.w);
        *(float4*)(outp + (long)row*768 + 256 + c4) = o;
    }
}

// ---------------- 4) fused attention (R8, unchanged) ----------------
#define SKS 268
#define SQS 516
#define OFF_SQ   17152
#define OFF_RED  21280
#define OFF_SC   25376
#define OFF_SA   25888
#define OFF_SMAX 26400
#define OFF_SRS  26408
#define OFF_RXY  26416
#define OFF_W1E  26544
#define OFF_W1O  26800
#define OFF_B1S  27056
#define ATTN_FLTS 27312
#define ATTN_SMEM (ATTN_FLTS*4)

__global__ __launch_bounds__(256, 2)
void attn_kernel(const float* __restrict__ r, const float* __restrict__ w1,
                 const float* __restrict__ b1) {
    extern __shared__ float smf[];
    float* skey = smf;
    float* sq   = smf + OFF_SQ;
    float* red  = smf + OFF_RED;
    float* sc   = smf + OFF_SC;
    float* sa   = smf + OFF_SA;
    float* smax = smf + OFF_SMAX;
    float* srs  = smf + OFF_SRS;
    float* rxy  = smf + OFF_RXY;
    float* w1e  = smf + OFF_W1E;
    float* w1o  = smf + OFF_W1O;
    float* b1s  = smf + OFF_B1S;

    int b = blockIdx.x, t = threadIdx.x;

    const float* keyb = g_key2 + (long)b * (64*256);
    #pragma unroll
    for (int q = 0; q < 16; q++) {
        int idx = t + 256*q;
        int row = idx >> 6, c4 = (idx & 63) * 4;
        *(float4*)(skey + row*SKS + c4) = *(const float4*)(keyb + row*256 + c4);
    }
    {
        const float4* qsrc = (const float4*)(g_qk + (long)b * 4096);
        #pragma unroll
        for (int q = 0; q < 4; q++) {
            int idx = t + 256*q;
            int row = idx >> 7, c = idx & 127;
            *(float4*)(sq + row*SQS + c*4) = qsrc[row*128 + c];
        }
    }
    if (t < 128) rxy[t] = r[b*128 + t];
    w1e[t] = w1[2*t]; w1o[t] = w1[2*t+1]; b1s[t] = b1[t];
    __syncthreads();

    {
        int s = t >> 5, lane = t & 31;
        int hq = lane >> 4, kq = lane & 15;
        int h0 = hq * 4, jb = s * 32;
        u64 acc2[4][4] = {};
        #pragma unroll
        for (int st = 0; st < 8; st++) {
            int jj = jb + st*4;
            ulonglong2 a0 = *(const ulonglong2*)(sq + (h0+0)*SQS + jj);
            ulonglong2 a1 = *(const ulonglong2*)(sq + (h0+1)*SQS + jj);
            ulonglong2 a2 = *(const ulonglong2*)(sq + (h0+2)*SQS + jj);
            ulonglong2 a3 = *(const ulonglong2*)(sq + (h0+3)*SQS + jj);
            #pragma unroll
            for (int m = 0; m < 4; m++) {
                ulonglong2 bv = *(const ulonglong2*)(skey + (kq + 16*m)*SKS + jj);
                acc2[0][m] = fma2(a0.x, bv.x, acc2[0][m]); acc2[0][m] = fma2(a0.y, bv.y, acc2[0][m]);
                acc2[1][m] = fma2(a1.x, bv.x, acc2[1][m]); acc2[1][m] = fma2(a1.y, bv.y, acc2[1][m]);
                acc2[2][m] = fma2(a2.x, bv.x, acc2[2][m]); acc2[2][m] = fma2(a2.y, bv.y, acc2[2][m]);
                acc2[3][m] = fma2(a3.x, bv.x, acc2[3][m]); acc2[3][m] = fma2(a3.y, bv.y, acc2[3][m]);
            }
        }
        u64 xs[4], ys[4];
        #pragma unroll
        for (int m = 0; m < 4; m++) {
            int k = kq + 16*m;
            xs[m] = splat2(rxy[2*k]);
            ys[m] = splat2(rxy[2*k+1]);
        }
        #pragma unroll
        for (int st = 0; st < 8; st++) {
            int w = jb + st*4, jj = 256 + w;
            ulonglong2 a0 = *(const ulonglong2*)(sq + (h0+0)*SQS + jj);
            ulonglong2 a1 = *(const ulonglong2*)(sq + (h0+1)*SQS + jj);
            ulonglong2 a2 = *(const ulonglong2*)(sq + (h0+2)*SQS + jj);
            ulonglong2 a3 = *(const ulonglong2*)(sq + (h0+3)*SQS + jj);
            ulonglong2 we2 = *(const ulonglong2*)(w1e + w);
            ulonglong2 wo2 = *(const ulonglong2*)(w1o + w);
            ulonglong2 bc2 = *(const ulonglong2*)(b1s + w);
            #pragma unroll
            for (int m = 0; m < 4; m++) {
                u64 bv01 = fma2(xs[m], we2.x, fma2(ys[m], wo2.x, bc2.x));
                u64 bv23 = fma2(xs[m], we2.y, fma2(ys[m], wo2.y, bc2.y));
                acc2[0][m] = fma2(a0.x, bv01, acc2[0][m]); acc2[0][m] = fma2(a0.y, bv23, acc2[0][m]);
                acc2[1][m] = fma2(a1.x, bv01, acc2[1][m]); acc2[1][m] = fma2(a1.y, bv23, acc2[1][m]);
                acc2[2][m] = fma2(a2.x, bv01, acc2[2][m]); acc2[2][m] = fma2(a2.y, bv23, acc2[2][m]);
                acc2[3][m] = fma2(a3.x, bv01, acc2[3][m]); acc2[3][m] = fma2(a3.y, bv23, acc2[3][m]);
            }
        }
        #pragma unroll
        for (int hi = 0; hi < 4; hi++)
            #pragma unroll
            for (int m = 0; m < 4; m++) {
                float2 u = unpack2(acc2[hi][m]);
                red[s*512 + (h0+hi)*64 + m*16 + kq] = u.x + u.y;
            }
    }
    __syncthreads();
    #pragma unroll
    for (int e0 = 0; e0 < 2; e0++) {
        int e = t + e0*256;
        float v = 0.f;
        #pragma unroll
        for (int s2 = 0; s2 < 8; s2++) v += red[s2*512 + e];
        sc[e] = v * 0.125f;
    }
    __syncthreads();

    if (t < 32) {
        int h = t >> 2, seg = t & 3;
        const float* p = sc + h*64 + seg*16;
        float mx = p[0];
        #pragma unroll
        for (int i = 1; i < 16; i++) mx = fmaxf(mx, p[i]);
        mx = fmaxf(mx, __shfl_xor_sync(0xffffffffu, mx, 1));
        mx = fmaxf(mx, __shfl_xor_sync(0xffffffffu, mx, 2));
        float sm = 0.f;
        #pragma unroll
        for (int i = 0; i < 16; i++) sm += __expf(p[i] - mx);
        sm += __shfl_xor_sync(0xffffffffu, sm, 1);
        sm += __shfl_xor_sync(0xffffffffu, sm, 2);
        if (seg == 0) { smax[h] = mx; srs[h] = 1.0f / sm; }
    }
    __syncthreads();
    sa[t]     = __expf(sc[t]     - smax[t >> 6])       * srs[t >> 6];
    sa[t+256] = __expf(sc[t+256] - smax[(t+256) >> 6]) * srs[(t+256) >> 6];
    __syncthreads();

    {
        int hq = t >> 7, jq = t & 127;
        int h0 = hq * 4, j0 = jq * 4;
        const float* sa0 = sa + (h0+0)*64;
        const float* sa1 = sa + (h0+1)*64;
        const float* sa2 = sa + (h0+2)*64;
        const float* sa3 = sa + (h0+3)*64;
        u64 acc2[4][2] = {};
        if (j0 < 256) {
            #pragma unroll
            for (int k4 = 0; k4 < 64; k4 += 4) {
                float4 av0 = *(const float4*)(sa0 + k4);
                float4 av1 = *(const float4*)(sa1 + k4);
                float4 av2 = *(const float4*)(sa2 + k4);
                float4 av3 = *(const float4*)(sa3 + k4);
                float a0r[4] = {av0.x, av0.y, av0.z, av0.w};
                float a1r[4] = {av1.x, av1.y, av1.z, av1.w};
                float a2r[4] = {av2.x, av2.y, av2.z, av2.w};
                float a3r[4] = {av3.x, av3.y, av3.z, av3.w};
                #pragma unroll
                for (int kk = 0; kk < 4; kk++) {
                    ulonglong2 bv = *(const ulonglong2*)(skey + (k4+kk)*SKS + j0);
                    u64 s0 = splat2(a0r[kk]), s1 = splat2(a1r[kk]);
                    u64 s2 = splat2(a2r[kk]), s3 = splat2(a3r[kk]);
                    acc2[0][0]=fma2(s0,bv.x,acc2[0][0]); acc2[0][1]=fma2(s0,bv.y,acc2[0][1]);
                    acc2[1][0]=fma2(s1,bv.x,acc2[1][0]); acc2[1][1]=fma2(s1,bv.y,acc2[1][1]);
                    acc2[2][0]=fma2(s2,bv.x,acc2[2][0]); acc2[2][1]=fma2(s2,bv.y,acc2[2][1]);
                    acc2[3][0]=fma2(s3,bv.x,acc2[3][0]); acc2[3][1]=fma2(s3,bv.y,acc2[3][1]);
                }
            }
        } else {
            int w = j0 - 256;
            ulonglong2 we2 = *(const ulonglong2*)(w1e + w);
            ulonglong2 wo2 = *(const ulonglong2*)(w1o + w);
            ulonglong2 bc2 = *(const ulonglong2*)(b1s + w);
            #pragma unroll
            for (int k4 = 0; k4 < 64; k4 += 4) {
                float4 av0 = *(const float4*)(sa0 + k4);
                float4 av1 = *(const float4*)(sa1 + k4);
                float4 av2 = *(const float4*)(sa2 + k4);
                float4 av3 = *(const float4*)(sa3 + k4);
                float a0r[4] = {av0.x, av0.y, av0.z, av0.w};
                float a1r[4] = {av1.x, av1.y, av1.z, av1.w};
                float a2r[4] = {av2.x, av2.y, av2.z, av2.w};
                float a3r[4] = {av3.x, av3.y, av3.z, av3.w};
                #pragma unroll
                for (int kk = 0; kk < 4; kk++) {
                    int k = k4 + kk;
                    u64 xs = splat2(rxy[2*k]), ys = splat2(rxy[2*k+1]);
                    u64 bv01 = fma2(xs, we2.x, fma2(ys, wo2.x, bc2.x));
                    u64 bv23 = fma2(xs, we2.y, fma2(ys, wo2.y, bc2.y));
                    u64 s0 = splat2(a0r[kk]), s1 = splat2(a1r[kk]);
                    u64 s2 = splat2(a2r[kk]), s3 = splat2(a3r[kk]);
                    acc2[0][0]=fma2(s0,bv01,acc2[0][0]); acc2[0][1]=fma2(s0,bv23,acc2[0][1]);
                    acc2[1][0]=fma2(s1,bv01,acc2[1][0]); acc2[1][1]=fma2(s1,bv23,acc2[1][1]);
                    acc2[2][0]=fma2(s2,bv01,acc2[2][0]); acc2[2][1]=fma2(s2,bv23,acc2[2][1]);
                    acc2[3][0]=fma2(s3,bv01,acc2[3][0]); acc2[3][1]=fma2(s3,bv23,acc2[3][1]);
                }
            }
        }
        float* ctxb = g_ctx + (long)b * 4096;
        #pragma unroll
        for (int hi = 0; hi < 4; hi++) {
            float2 u0 = unpack2(acc2[hi][0]);
            float2 u1 = unpack2(acc2[hi][1]);
            *(float4*)(ctxb + (h0+hi)*512 + j0) = make_float4(u0.x, u0.y, u1.x, u1.y);
        }
    }
}

// ---------------- host launcher ----------------
extern "C" void kernel_launch(void* const* d_in, const int* in_sizes, int n_in,
                              void* d_out, int out_size) {
    const float* Z          = (const float*)d_in[0];
    const float* Q          = (const float*)d_in[1];
    const float* q_z        = (const float*)d_in[2];
    const float* r          = (const float*)d_in[3];
    const float* w1         = (const float*)d_in[4];
    const float* b1         = (const float*)d_in[5];
    const float* w2         = (const float*)d_in[6];
    const float* b2         = (const float*)d_in[7];
    const float* in_proj_w  = (const float*)d_in[8];
    const float* in_proj_b  = (const float*)d_in[9];
    const float* out_proj_w = (const float*)d_in[10];
    const float* out_proj_b = (const float*)d_in[11];
    float* outp = (float*)d_out;

    cudaFuncSetAttribute(attn_kernel,
                         cudaFuncAttributeMaxDynamicSharedMemorySize, ATTN_SMEM);

    // 1) transpose Z -> Zt
    transpose_kernel<<<dim3((HWn*HWn)/32, Cn/32), dim3(32, 8)>>>(Z);

    // 2) fat: gemm1(fused query) + qz->out copy + interp
    fat_kernel<<<FAT_INTERP_OFF + NPn/32, 256>>>(
        r, q_z, Q, w2, b2, in_proj_w, in_proj_b, outp);

    // 3) qk
    qk_kernel<<<dim3(En/64, SQn/128, NHn), 256>>>(in_proj_w);

    // 4) attention
    attn_kernel<<<SQn, 256, ATTN_SMEM>>>(r, w1, b1);

    // 5) v gemm, K-split (256 blocks)
    vsplit_kernel<<<dim3(1, SQn/128, 16), 256>>>(in_proj_w);

    // 6) out gemm, K-split (256 blocks), A = vp0+vp1+bv
    outsplit_kernel<<<dim3(En/64, SQn/128, 2), 256>>>(in_proj_b, out_proj_w);

    // 7) finalize: outp[:,256:768] = op0 + op1 + bo
    finalize_kernel<<<512, 256>>>(out_proj_b, outp);
}